// round 11
// baseline (speedup 1.0000x reference)
#include <cuda_runtime.h>
#include <cuda_bf16.h>
#include <cstdint>
#include <math.h>

#define N_NODES 100000
#define NFEAT   512
#define NHID    256
#define NCLASS  40
#define NEDGE   1600000
#define KHOPS   10
#define ALPHA_F 0.1f

// ---------------- scratch (device globals; no allocs allowed) ----------------
__device__ __nv_bfloat16  g_hb [(size_t)N_NODES * NHID];   // 51.2 MB (bf16 h)
__device__ float          g_h2 [(size_t)N_NODES * NCLASS]; // 16 MB
__device__ float          g_za [(size_t)N_NODES * NCLASS]; // 16 MB
__device__ __nv_bfloat16  g_xb [(size_t)N_NODES * NFEAT];  // 102.4 MB (bf16 x)
__device__ __nv_bfloat16  g_w1b[(size_t)NHID * NFEAT];     // 256 KB (W1^T bf16 [N][K])
__device__ __nv_bfloat16  g_w2t[(size_t)NCLASS * NHID];    // 20 KB (W2^T bf16 [N][K])
__device__ int   g_deg[N_NODES];
__device__ int   g_rowptr[N_NODES + 1];
__device__ int   g_cursor[N_NODES];
__device__ int2  g_cedge[NEDGE];                           // 12.8 MB {src, val bits}

// ---------------- cp.async helpers ----------------
__device__ __forceinline__ void cp_async16(uint32_t saddr, const void* gaddr) {
    asm volatile("cp.async.cg.shared.global [%0], [%1], 16;\n" :: "r"(saddr), "l"(gaddr));
}
__device__ __forceinline__ void cp_commit() {
    asm volatile("cp.async.commit_group;\n" ::: "memory");
}
__device__ __forceinline__ void cp_wait1() {
    asm volatile("cp.async.wait_group 1;\n" ::: "memory");
}
__device__ __forceinline__ void ldsm_x4(uint32_t& r0, uint32_t& r1, uint32_t& r2,
                                        uint32_t& r3, uint32_t addr) {
    asm volatile("ldmatrix.sync.aligned.m8n8.x4.shared.b16 {%0,%1,%2,%3}, [%4];"
                 : "=r"(r0), "=r"(r1), "=r"(r2), "=r"(r3) : "r"(addr));
}

// ---------------- bf16 conversions ----------------
__global__ void __launch_bounds__(256)
conv_x_kernel(const float* __restrict__ x, __nv_bfloat16* __restrict__ xb)
{
    int i = blockIdx.x * 256 + threadIdx.x;         // per 8 floats
    const int n8 = N_NODES * NFEAT / 8;
    if (i < n8) {
        float4 a = ((const float4*)x)[2 * i];
        float4 b = ((const float4*)x)[2 * i + 1];
        __nv_bfloat162 p0 = __floats2bfloat162_rn(a.x, a.y);
        __nv_bfloat162 p1 = __floats2bfloat162_rn(a.z, a.w);
        __nv_bfloat162 p2 = __floats2bfloat162_rn(b.x, b.y);
        __nv_bfloat162 p3 = __floats2bfloat162_rn(b.z, b.w);
        uint4 o;
        o.x = *reinterpret_cast<unsigned*>(&p0);
        o.y = *reinterpret_cast<unsigned*>(&p1);
        o.z = *reinterpret_cast<unsigned*>(&p2);
        o.w = *reinterpret_cast<unsigned*>(&p3);
        ((uint4*)xb)[i] = o;
    }
}

__global__ void __launch_bounds__(256)
conv_w1_kernel(const float* __restrict__ W1, __nv_bfloat16* __restrict__ w1b)
{
    int id = blockIdx.x * 256 + threadIdx.x;        // (n,k), k fast
    if (id < NHID * NFEAT) {
        int n = id >> 9;
        int k = id & 511;
        w1b[id] = __float2bfloat16(W1[(size_t)k * NHID + n]);
    }
}

__global__ void __launch_bounds__(256)
conv_w2_kernel(const float* __restrict__ W2, __nv_bfloat16* __restrict__ w2t)
{
    int id = blockIdx.x * 256 + threadIdx.x;        // (n,k), k fast
    if (id < NCLASS * NHID) {
        int n = id >> 8;
        int k = id & 255;
        w2t[id] = __float2bfloat16(W2[(size_t)k * NCLASS + n]);
    }
}

// ---------------- GEMM1: hb = relu(x @ W1 + b1) via bf16 mma.sync + ldmatrix -
#define G1_BK  32
#define G1_STR 40

__global__ void __launch_bounds__(256, 2)
gemm1_bf16_kernel(const __nv_bfloat16* __restrict__ xb,
                  const __nv_bfloat16* __restrict__ w1b,
                  const float* __restrict__ b1, __nv_bfloat16* __restrict__ hb)
{
    __shared__ __nv_bfloat16 As[2][128][G1_STR];
    __shared__ __nv_bfloat16 Bs[2][128][G1_STR];

    const int tid  = threadIdx.x;
    const int warp = tid >> 5;
    const int lane = tid & 31;
    const int grp  = lane >> 2;
    const int tig  = lane & 3;
    const int warp_m = warp & 1;
    const int warp_n = warp >> 1;

    const int m0 = blockIdx.x * 128;
    const int n0 = blockIdx.y * 128;

    const uint32_t sA = (uint32_t)__cvta_generic_to_shared(&As[0][0][0]);
    const uint32_t sB = (uint32_t)__cvta_generic_to_shared(&Bs[0][0][0]);
    const uint32_t BUFB = 128u * G1_STR * 2u;

    const int lm_row = lane & 15;
    const int lm_kof = (lane >> 4) * 8;

    float acc[4][4][4];
    #pragma unroll
    for (int i = 0; i < 4; i++)
        #pragma unroll
        for (int j = 0; j < 4; j++)
            #pragma unroll
            for (int r = 0; r < 4; r++) acc[i][j][r] = 0.f;

    const int c0 = tid, c1 = tid + 256;
    const int ar0 = c0 >> 2, ak0 = (c0 & 3) * 8;
    const int ar1 = c1 >> 2, ak1 = (c1 & 3) * 8;
    const int gr0 = min(m0 + ar0, N_NODES - 1);
    const int gr1 = min(m0 + ar1, N_NODES - 1);

    const int NT = NFEAT / G1_BK;  // 16

    auto load_tile = [&](int kt, int b) {
        const int kb = kt * G1_BK;
        const uint32_t ab = sA + (uint32_t)b * BUFB;
        const uint32_t bb = sB + (uint32_t)b * BUFB;
        cp_async16(ab + (uint32_t)((ar0 * G1_STR + ak0) * 2),
                   xb + (size_t)gr0 * NFEAT + kb + ak0);
        cp_async16(ab + (uint32_t)((ar1 * G1_STR + ak1) * 2),
                   xb + (size_t)gr1 * NFEAT + kb + ak1);
        cp_async16(bb + (uint32_t)((ar0 * G1_STR + ak0) * 2),
                   w1b + (size_t)(n0 + ar0) * NFEAT + kb + ak0);
        cp_async16(bb + (uint32_t)((ar1 * G1_STR + ak1) * 2),
                   w1b + (size_t)(n0 + ar1) * NFEAT + kb + ak1);
    };

    load_tile(0, 0);
    cp_commit();

    for (int kt = 0; kt < NT; kt++) {
        if (kt + 1 < NT) load_tile(kt + 1, (kt + 1) & 1);
        cp_commit();
        cp_wait1();
        __syncthreads();

        const int buf = kt & 1;
        const uint32_t abuf = sA + (uint32_t)buf * BUFB;
        const uint32_t bbuf = sB + (uint32_t)buf * BUFB;
        #pragma unroll
        for (int ks = 0; ks < 2; ks++) {
            const int kb = ks * 16 + lm_kof;
            uint32_t a[4][4], b[4][2];
            #pragma unroll
            for (int mf = 0; mf < 4; mf++) {
                const int r = warp_m * 64 + mf * 16 + lm_row;
                ldsm_x4(a[mf][0], a[mf][1], a[mf][2], a[mf][3],
                        abuf + (uint32_t)((r * G1_STR + kb) * 2));
            }
            #pragma unroll
            for (int np = 0; np < 2; np++) {
                const int cn = warp_n * 32 + np * 16 + lm_row;
                ldsm_x4(b[2*np][0], b[2*np + 1][0], b[2*np][1], b[2*np + 1][1],
                        bbuf + (uint32_t)((cn * G1_STR + kb) * 2));
            }
            #pragma unroll
            for (int mf = 0; mf < 4; mf++)
                #pragma unroll
                for (int nf = 0; nf < 4; nf++) {
                    asm volatile(
                        "mma.sync.aligned.m16n8k16.row.col.f32.bf16.bf16.f32 "
                        "{%0,%1,%2,%3}, {%4,%5,%6,%7}, {%8,%9}, {%0,%1,%2,%3};\n"
                        : "+f"(acc[mf][nf][0]), "+f"(acc[mf][nf][1]),
                          "+f"(acc[mf][nf][2]), "+f"(acc[mf][nf][3])
                        : "r"(a[mf][0]), "r"(a[mf][1]), "r"(a[mf][2]), "r"(a[mf][3]),
                          "r"(b[nf][0]), "r"(b[nf][1]));
                }
        }
        __syncthreads();
    }

    #pragma unroll
    for (int nf = 0; nf < 4; nf++) {
        const int cg = n0 + warp_n * 32 + nf * 8 + 2 * tig;
        const float bx = b1[cg], by = b1[cg + 1];
        #pragma unroll
        for (int mf = 0; mf < 4; mf++) {
            const int rg = m0 + warp_m * 64 + mf * 16 + grp;
            if (rg < N_NODES) {
                __nv_bfloat162 o = __floats2bfloat162_rn(
                    fmaxf(acc[mf][nf][0] + bx, 0.f),
                    fmaxf(acc[mf][nf][1] + by, 0.f));
                *(uint32_t*)&hb[(size_t)rg * NHID + cg] = *reinterpret_cast<uint32_t*>(&o);
            }
            if (rg + 8 < N_NODES) {
                __nv_bfloat162 o = __floats2bfloat162_rn(
                    fmaxf(acc[mf][nf][2] + bx, 0.f),
                    fmaxf(acc[mf][nf][3] + by, 0.f));
                *(uint32_t*)&hb[(size_t)(rg + 8) * NHID + cg] = *reinterpret_cast<uint32_t*>(&o);
            }
        }
    }
}

// ---------------- GEMM2: h2 = hb @ W2 + b2 via bf16 mma.sync -----------------
#define G2_ASTR 24
#define G2_BSTR 264

__global__ void __launch_bounds__(128)
gemm2_bf16_kernel(const __nv_bfloat16* __restrict__ hb,
                  const __nv_bfloat16* __restrict__ w2t,
                  const float* __restrict__ b2, float* __restrict__ h2)
{
    __shared__ __nv_bfloat16 As[2][256][G2_ASTR];
    __shared__ __nv_bfloat16 Bs[NCLASS][G2_BSTR];

    const int tid  = threadIdx.x;
    const int warp = tid >> 5;
    const int lane = tid & 31;
    const int grp  = lane >> 2;
    const int tig  = lane & 3;

    const int r0 = blockIdx.x * 256;

    const uint32_t sA = (uint32_t)__cvta_generic_to_shared(&As[0][0][0]);
    const uint32_t ABUF = 256u * G2_ASTR * 2u;

    #pragma unroll
    for (int i = 0; i < 10; i++) {
        int c = tid + i * 128;
        int n = c >> 5;
        int ks = (c & 31) * 8;
        *(uint4*)&Bs[n][ks] = *(const uint4*)&w2t[(size_t)n * NHID + ks];
    }

    float acc[4][5][4];
    #pragma unroll
    for (int i = 0; i < 4; i++)
        #pragma unroll
        for (int j = 0; j < 5; j++)
            #pragma unroll
            for (int r = 0; r < 4; r++) acc[i][j][r] = 0.f;

    const int NT = NHID / 16;   // 16
    auto load_tile = [&](int kt, int b) {
        const uint32_t ab = sA + (uint32_t)b * ABUF;
        #pragma unroll
        for (int i = 0; i < 4; i++) {
            int c = tid + i * 128;
            int row = c >> 1;
            int seg = (c & 1) * 8;
            int gr = min(r0 + row, N_NODES - 1);
            cp_async16(ab + (uint32_t)((row * G2_ASTR + seg) * 2),
                       hb + (size_t)gr * NHID + kt * 16 + seg);
        }
    };

    load_tile(0, 0);
    cp_commit();
    __syncthreads();

    for (int kt = 0; kt < NT; kt++) {
        if (kt + 1 < NT) load_tile(kt + 1, (kt + 1) & 1);
        cp_commit();
        cp_wait1();
        __syncthreads();

        const int buf = kt & 1;
        uint32_t a[4][4], b[5][2];
        #pragma unroll
        for (int mf = 0; mf < 4; mf++) {
            const int r = warp * 64 + mf * 16 + grp;
            a[mf][0] = *(const uint32_t*)&As[buf][r    ][tig * 2    ];
            a[mf][1] = *(const uint32_t*)&As[buf][r + 8][tig * 2    ];
            a[mf][2] = *(const uint32_t*)&As[buf][r    ][tig * 2 + 8];
            a[mf][3] = *(const uint32_t*)&As[buf][r + 8][tig * 2 + 8];
        }
        #pragma unroll
        for (int nf = 0; nf < 5; nf++) {
            const int cn = nf * 8 + grp;
            b[nf][0] = *(const uint32_t*)&Bs[cn][kt * 16 + tig * 2    ];
            b[nf][1] = *(const uint32_t*)&Bs[cn][kt * 16 + tig * 2 + 8];
        }
        #pragma unroll
        for (int mf = 0; mf < 4; mf++)
            #pragma unroll
            for (int nf = 0; nf < 5; nf++) {
                asm volatile(
                    "mma.sync.aligned.m16n8k16.row.col.f32.bf16.bf16.f32 "
                    "{%0,%1,%2,%3}, {%4,%5,%6,%7}, {%8,%9}, {%0,%1,%2,%3};\n"
                    : "+f"(acc[mf][nf][0]), "+f"(acc[mf][nf][1]),
                      "+f"(acc[mf][nf][2]), "+f"(acc[mf][nf][3])
                    : "r"(a[mf][0]), "r"(a[mf][1]), "r"(a[mf][2]), "r"(a[mf][3]),
                      "r"(b[nf][0]), "r"(b[nf][1]));
            }
        __syncthreads();
    }

    #pragma unroll
    for (int nf = 0; nf < 5; nf++) {
        const int col = nf * 8 + 2 * tig;
        const float bx = b2[col], by = b2[col + 1];
        #pragma unroll
        for (int mf = 0; mf < 4; mf++) {
            const int rg = r0 + warp * 64 + mf * 16 + grp;
            if (rg < N_NODES) {
                float2 o;
                o.x = acc[mf][nf][0] + bx;
                o.y = acc[mf][nf][1] + by;
                *(float2*)&h2[(size_t)rg * NCLASS + col] = o;
            }
            if (rg + 8 < N_NODES) {
                float2 o;
                o.x = acc[mf][nf][2] + bx;
                o.y = acc[mf][nf][3] + by;
                *(float2*)&h2[(size_t)(rg + 8) * NCLASS + col] = o;
            }
        }
    }
}

// ================= CSR build (by dst), rebuilt deterministically each call ===
__global__ void __launch_bounds__(256)
zero_deg_kernel(int* __restrict__ deg)
{
    int i = blockIdx.x * 256 + threadIdx.x;
    if (i < N_NODES) deg[i] = 0;
}

__global__ void __launch_bounds__(256)
hist_kernel(const int* __restrict__ edst, int* __restrict__ deg)
{
    int e = blockIdx.x * 256 + threadIdx.x;
    if (e < NEDGE) atomicAdd(&deg[edst[e]], 1);
}

__global__ void __launch_bounds__(1024)
scan_kernel(const int* __restrict__ deg, int* __restrict__ rowptr,
            int* __restrict__ cursor)
{
    __shared__ int part[1024];
    const int tid = threadIdx.x;
    const int CH = (N_NODES + 1023) / 1024;   // 98
    const int base = tid * CH;

    int s = 0;
    for (int i = 0; i < CH; i++) {
        int idx = base + i;
        if (idx < N_NODES) s += deg[idx];
    }
    part[tid] = s;
    __syncthreads();
    for (int off = 1; off < 1024; off <<= 1) {
        int v = (tid >= off) ? part[tid - off] : 0;
        __syncthreads();
        part[tid] += v;
        __syncthreads();
    }
    int run = (tid > 0) ? part[tid - 1] : 0;
    for (int i = 0; i < CH; i++) {
        int idx = base + i;
        if (idx < N_NODES) {
            rowptr[idx] = run;
            cursor[idx] = run;
            run += deg[idx];
        }
    }
    if (tid == 1023) rowptr[N_NODES] = run;
}

__global__ void __launch_bounds__(256)
scatter_kernel(const int* __restrict__ esrc, const int* __restrict__ edst,
               const float* __restrict__ eval_, int* __restrict__ cursor,
               int2* __restrict__ cedge)
{
    int e = blockIdx.x * 256 + threadIdx.x;
    if (e < NEDGE) {
        int d = edst[e];
        int slot = atomicAdd(&cursor[d], 1);
        cedge[slot] = make_int2(esrc[e],
                                __float_as_int((1.0f - ALPHA_F) * eval_[e]));
    }
}

// ======== propagation hop (warp-per-dst): zout[d] = a*h2[d] + sum ev*zin[s] ==
// lane = class (lanes 0-31 -> 0-31; lanes 0-7 also -> 32-39). Edge record read
// once per warp (broadcast). FINAL variant fuses log_softmax.
template<bool FINAL>
__global__ void __launch_bounds__(256)
prop_warp_kernel(const int* __restrict__ rowptr, const int2* __restrict__ cedge,
                 const float* __restrict__ h2,
                 const float* __restrict__ zin, float* __restrict__ zout)
{
    const int dst  = blockIdx.x * 8 + (threadIdx.x >> 5);   // grid exactly covers
    const int lane = threadIdx.x & 31;
    if (dst >= N_NODES) return;
    const bool hi = lane < (NCLASS - 32);   // lanes 0..7 carry classes 32..39

    int e  = rowptr[dst];
    const int e1 = rowptr[dst + 1];

    const float* h2r = h2 + (size_t)dst * NCLASS;
    float a0 = ALPHA_F * h2r[lane];
    float a1 = hi ? ALPHA_F * h2r[32 + lane] : 0.f;
    float b0 = 0.f, b1 = 0.f;

    for (; e + 2 <= e1; e += 2) {
        int2 d0 = cedge[e];
        int2 d1 = cedge[e + 1];
        const float* z0 = zin + (size_t)d0.x * NCLASS;
        const float* z1 = zin + (size_t)d1.x * NCLASS;
        float v0 = __int_as_float(d0.y);
        float v1 = __int_as_float(d1.y);
        a0 = fmaf(v0, z0[lane], a0);
        b0 = fmaf(v1, z1[lane], b0);
        if (hi) {
            a1 = fmaf(v0, z0[32 + lane], a1);
            b1 = fmaf(v1, z1[32 + lane], b1);
        }
    }
    if (e < e1) {
        int2 d0 = cedge[e];
        const float* z0 = zin + (size_t)d0.x * NCLASS;
        float v0 = __int_as_float(d0.y);
        a0 = fmaf(v0, z0[lane], a0);
        if (hi) a1 = fmaf(v0, z0[32 + lane], a1);
    }
    a0 += b0;
    a1 += b1;

    float* orow = zout + (size_t)dst * NCLASS;
    if (!FINAL) {
        orow[lane] = a0;
        if (hi) orow[32 + lane] = a1;
    } else {
        // fused log_softmax over the 40 values held by this warp
        float m = hi ? fmaxf(a0, a1) : a0;
        #pragma unroll
        for (int o = 16; o > 0; o >>= 1) m = fmaxf(m, __shfl_xor_sync(0xffffffffu, m, o));
        float s = __expf(a0 - m) + (hi ? __expf(a1 - m) : 0.f);
        #pragma unroll
        for (int o = 16; o > 0; o >>= 1) s += __shfl_xor_sync(0xffffffffu, s, o);
        float lse = m + __logf(s);
        orow[lane] = a0 - lse;
        if (hi) orow[32 + lane] = a1 - lse;
    }
}

// ---------------- launch ----------------
extern "C" void kernel_launch(void* const* d_in, const int* in_sizes, int n_in,
                              void* d_out, int out_size)
{
    const float* x     = (const float*)d_in[0];
    const int*   esrc  = (const int*)  d_in[1];
    const int*   edst  = (const int*)  d_in[2];
    const float* eval_ = (const float*)d_in[3];
    const float* W1    = (const float*)d_in[4];
    const float* b1    = (const float*)d_in[5];
    const float* W2    = (const float*)d_in[6];
    const float* b2    = (const float*)d_in[7];
    float* out = (float*)d_out;

    float *h2, *za;
    __nv_bfloat16 *hb, *xb, *w1b, *w2t;
    int *deg, *rowptr, *cursor;
    int2 *cedge;
    cudaGetSymbolAddress((void**)&hb,     g_hb);
    cudaGetSymbolAddress((void**)&h2,     g_h2);
    cudaGetSymbolAddress((void**)&za,     g_za);
    cudaGetSymbolAddress((void**)&xb,     g_xb);
    cudaGetSymbolAddress((void**)&w1b,    g_w1b);
    cudaGetSymbolAddress((void**)&w2t,    g_w2t);
    cudaGetSymbolAddress((void**)&deg,    g_deg);
    cudaGetSymbolAddress((void**)&rowptr, g_rowptr);
    cudaGetSymbolAddress((void**)&cursor, g_cursor);
    cudaGetSymbolAddress((void**)&cedge,  g_cedge);

    // bf16 conversions
    conv_x_kernel<<<(N_NODES * NFEAT / 8 + 255) / 256, 256>>>(x, xb);
    conv_w1_kernel<<<(NHID * NFEAT + 255) / 256, 256>>>(W1, w1b);
    conv_w2_kernel<<<(NCLASS * NHID + 255) / 256, 256>>>(W2, w2t);

    // GEMM1 (bf16 mma.sync + ldmatrix) -> hb (bf16)
    dim3 g1((N_NODES + 127) / 128, NHID / 128);   // (782, 2)
    gemm1_bf16_kernel<<<g1, 256>>>(xb, w1b, b1, hb);

    // GEMM2 (bf16 mma.sync) -> h2 (fp32)
    gemm2_bf16_kernel<<<(N_NODES + 255) / 256, 128>>>(hb, w2t, b2, h2);

    // CSR build
    zero_deg_kernel<<<(N_NODES + 255) / 256, 256>>>(deg);
    hist_kernel<<<(NEDGE + 255) / 256, 256>>>(edst, deg);
    scan_kernel<<<1, 1024>>>(deg, rowptr, cursor);
    scatter_kernel<<<(NEDGE + 255) / 256, 256>>>(esrc, edst, eval_, cursor, cedge);

    const int prop_blocks = (N_NODES + 7) / 8;    // 12500, warp-per-dst
    const float* zin = h2;
    for (int i = 0; i < KHOPS - 1; i++) {
        float* zout = (i % 2 == 0) ? za : out;
        prop_warp_kernel<false><<<prop_blocks, 256>>>(rowptr, cedge, h2, zin, zout);
        zin = zout;
    }
    // last hop (i=9): zin = out (after 9 hops: h2->za->out->...->out at i=8)
    prop_warp_kernel<true><<<prop_blocks, 256>>>(rowptr, cedge, h2, zin, out);
}

// round 12
// speedup vs baseline: 2.3045x; 2.3045x over previous
#include <cuda_runtime.h>
#include <cuda_bf16.h>
#include <cstdint>
#include <math.h>

#define N_NODES 100000
#define NFEAT   512
#define NHID    256
#define NCLASS  40
#define NEDGE   1600000
#define KHOPS   10
#define ALPHA_F 0.1f
#define NBLK    391   // ceil(100000/256)

// ---------------- scratch (device globals; no allocs allowed) ----------------
__device__ __nv_bfloat16  g_hb [(size_t)N_NODES * NHID];   // 51.2 MB (bf16 h)
__device__ float          g_h2 [(size_t)N_NODES * NCLASS]; // 16 MB
__device__ float          g_za [(size_t)N_NODES * NCLASS]; // 16 MB
__device__ __nv_bfloat16  g_xb [(size_t)N_NODES * NFEAT];  // 102.4 MB (bf16 x)
__device__ __nv_bfloat16  g_w1b[(size_t)NHID * NFEAT];     // 256 KB (W1^T bf16 [N][K])
__device__ __nv_bfloat16  g_w2t[(size_t)NCLASS * NHID];    // 20 KB (W2^T bf16 [N][K])
__device__ int   g_deg[N_NODES];
__device__ int   g_rowptr[N_NODES + 1];
__device__ int   g_cursor[N_NODES];
__device__ int   g_bpart[512];
__device__ int   g_boff[512];
__device__ int2  g_cedge[NEDGE];                           // 12.8 MB {src, val bits}

// ---------------- cp.async helpers ----------------
__device__ __forceinline__ void cp_async16(uint32_t saddr, const void* gaddr) {
    asm volatile("cp.async.cg.shared.global [%0], [%1], 16;\n" :: "r"(saddr), "l"(gaddr));
}
__device__ __forceinline__ void cp_commit() {
    asm volatile("cp.async.commit_group;\n" ::: "memory");
}
__device__ __forceinline__ void cp_wait1() {
    asm volatile("cp.async.wait_group 1;\n" ::: "memory");
}
__device__ __forceinline__ void ldsm_x4(uint32_t& r0, uint32_t& r1, uint32_t& r2,
                                        uint32_t& r3, uint32_t addr) {
    asm volatile("ldmatrix.sync.aligned.m8n8.x4.shared.b16 {%0,%1,%2,%3}, [%4];"
                 : "=r"(r0), "=r"(r1), "=r"(r2), "=r"(r3) : "r"(addr));
}

// ---------------- bf16 conversions ----------------
__global__ void __launch_bounds__(256)
conv_x_kernel(const float* __restrict__ x, __nv_bfloat16* __restrict__ xb)
{
    int i = blockIdx.x * 256 + threadIdx.x;         // per 8 floats
    const int n8 = N_NODES * NFEAT / 8;
    if (i < n8) {
        float4 a = ((const float4*)x)[2 * i];
        float4 b = ((const float4*)x)[2 * i + 1];
        __nv_bfloat162 p0 = __floats2bfloat162_rn(a.x, a.y);
        __nv_bfloat162 p1 = __floats2bfloat162_rn(a.z, a.w);
        __nv_bfloat162 p2 = __floats2bfloat162_rn(b.x, b.y);
        __nv_bfloat162 p3 = __floats2bfloat162_rn(b.z, b.w);
        uint4 o;
        o.x = *reinterpret_cast<unsigned*>(&p0);
        o.y = *reinterpret_cast<unsigned*>(&p1);
        o.z = *reinterpret_cast<unsigned*>(&p2);
        o.w = *reinterpret_cast<unsigned*>(&p3);
        ((uint4*)xb)[i] = o;
    }
}

__global__ void __launch_bounds__(256)
conv_w1_kernel(const float* __restrict__ W1, __nv_bfloat16* __restrict__ w1b)
{
    int id = blockIdx.x * 256 + threadIdx.x;        // (n,k), k fast
    if (id < NHID * NFEAT) {
        int n = id >> 9;
        int k = id & 511;
        w1b[id] = __float2bfloat16(W1[(size_t)k * NHID + n]);
    }
}

__global__ void __launch_bounds__(256)
conv_w2_kernel(const float* __restrict__ W2, __nv_bfloat16* __restrict__ w2t)
{
    int id = blockIdx.x * 256 + threadIdx.x;        // (n,k), k fast
    if (id < NCLASS * NHID) {
        int n = id >> 8;
        int k = id & 255;
        w2t[id] = __float2bfloat16(W2[(size_t)k * NCLASS + n]);
    }
}

// ---------------- GEMM1: hb = relu(x @ W1 + b1) via bf16 mma.sync + ldmatrix -
#define G1_BK  32
#define G1_STR 40

__global__ void __launch_bounds__(256, 2)
gemm1_bf16_kernel(const __nv_bfloat16* __restrict__ xb,
                  const __nv_bfloat16* __restrict__ w1b,
                  const float* __restrict__ b1, __nv_bfloat16* __restrict__ hb)
{
    __shared__ __nv_bfloat16 As[2][128][G1_STR];
    __shared__ __nv_bfloat16 Bs[2][128][G1_STR];

    const int tid  = threadIdx.x;
    const int warp = tid >> 5;
    const int lane = tid & 31;
    const int grp  = lane >> 2;
    const int tig  = lane & 3;
    const int warp_m = warp & 1;
    const int warp_n = warp >> 1;

    const int m0 = blockIdx.x * 128;
    const int n0 = blockIdx.y * 128;

    const uint32_t sA = (uint32_t)__cvta_generic_to_shared(&As[0][0][0]);
    const uint32_t sB = (uint32_t)__cvta_generic_to_shared(&Bs[0][0][0]);
    const uint32_t BUFB = 128u * G1_STR * 2u;

    const int lm_row = lane & 15;
    const int lm_kof = (lane >> 4) * 8;

    float acc[4][4][4];
    #pragma unroll
    for (int i = 0; i < 4; i++)
        #pragma unroll
        for (int j = 0; j < 4; j++)
            #pragma unroll
            for (int r = 0; r < 4; r++) acc[i][j][r] = 0.f;

    const int c0 = tid, c1 = tid + 256;
    const int ar0 = c0 >> 2, ak0 = (c0 & 3) * 8;
    const int ar1 = c1 >> 2, ak1 = (c1 & 3) * 8;
    const int gr0 = min(m0 + ar0, N_NODES - 1);
    const int gr1 = min(m0 + ar1, N_NODES - 1);

    const int NT = NFEAT / G1_BK;  // 16

    auto load_tile = [&](int kt, int b) {
        const int kb = kt * G1_BK;
        const uint32_t ab = sA + (uint32_t)b * BUFB;
        const uint32_t bb = sB + (uint32_t)b * BUFB;
        cp_async16(ab + (uint32_t)((ar0 * G1_STR + ak0) * 2),
                   xb + (size_t)gr0 * NFEAT + kb + ak0);
        cp_async16(ab + (uint32_t)((ar1 * G1_STR + ak1) * 2),
                   xb + (size_t)gr1 * NFEAT + kb + ak1);
        cp_async16(bb + (uint32_t)((ar0 * G1_STR + ak0) * 2),
                   w1b + (size_t)(n0 + ar0) * NFEAT + kb + ak0);
        cp_async16(bb + (uint32_t)((ar1 * G1_STR + ak1) * 2),
                   w1b + (size_t)(n0 + ar1) * NFEAT + kb + ak1);
    };

    load_tile(0, 0);
    cp_commit();

    for (int kt = 0; kt < NT; kt++) {
        if (kt + 1 < NT) load_tile(kt + 1, (kt + 1) & 1);
        cp_commit();
        cp_wait1();
        __syncthreads();

        const int buf = kt & 1;
        const uint32_t abuf = sA + (uint32_t)buf * BUFB;
        const uint32_t bbuf = sB + (uint32_t)buf * BUFB;
        #pragma unroll
        for (int ks = 0; ks < 2; ks++) {
            const int kb = ks * 16 + lm_kof;
            uint32_t a[4][4], b[4][2];
            #pragma unroll
            for (int mf = 0; mf < 4; mf++) {
                const int r = warp_m * 64 + mf * 16 + lm_row;
                ldsm_x4(a[mf][0], a[mf][1], a[mf][2], a[mf][3],
                        abuf + (uint32_t)((r * G1_STR + kb) * 2));
            }
            #pragma unroll
            for (int np = 0; np < 2; np++) {
                const int cn = warp_n * 32 + np * 16 + lm_row;
                ldsm_x4(b[2*np][0], b[2*np + 1][0], b[2*np][1], b[2*np + 1][1],
                        bbuf + (uint32_t)((cn * G1_STR + kb) * 2));
            }
            #pragma unroll
            for (int mf = 0; mf < 4; mf++)
                #pragma unroll
                for (int nf = 0; nf < 4; nf++) {
                    asm volatile(
                        "mma.sync.aligned.m16n8k16.row.col.f32.bf16.bf16.f32 "
                        "{%0,%1,%2,%3}, {%4,%5,%6,%7}, {%8,%9}, {%0,%1,%2,%3};\n"
                        : "+f"(acc[mf][nf][0]), "+f"(acc[mf][nf][1]),
                          "+f"(acc[mf][nf][2]), "+f"(acc[mf][nf][3])
                        : "r"(a[mf][0]), "r"(a[mf][1]), "r"(a[mf][2]), "r"(a[mf][3]),
                          "r"(b[nf][0]), "r"(b[nf][1]));
                }
        }
        __syncthreads();
    }

    #pragma unroll
    for (int nf = 0; nf < 4; nf++) {
        const int cg = n0 + warp_n * 32 + nf * 8 + 2 * tig;
        const float bx = b1[cg], by = b1[cg + 1];
        #pragma unroll
        for (int mf = 0; mf < 4; mf++) {
            const int rg = m0 + warp_m * 64 + mf * 16 + grp;
            if (rg < N_NODES) {
                __nv_bfloat162 o = __floats2bfloat162_rn(
                    fmaxf(acc[mf][nf][0] + bx, 0.f),
                    fmaxf(acc[mf][nf][1] + by, 0.f));
                *(uint32_t*)&hb[(size_t)rg * NHID + cg] = *reinterpret_cast<uint32_t*>(&o);
            }
            if (rg + 8 < N_NODES) {
                __nv_bfloat162 o = __floats2bfloat162_rn(
                    fmaxf(acc[mf][nf][2] + bx, 0.f),
                    fmaxf(acc[mf][nf][3] + by, 0.f));
                *(uint32_t*)&hb[(size_t)(rg + 8) * NHID + cg] = *reinterpret_cast<uint32_t*>(&o);
            }
        }
    }
}

// ---------------- GEMM2: h2 = hb @ W2 + b2 via bf16 mma.sync -----------------
#define G2_ASTR 24
#define G2_BSTR 264

__global__ void __launch_bounds__(128)
gemm2_bf16_kernel(const __nv_bfloat16* __restrict__ hb,
                  const __nv_bfloat16* __restrict__ w2t,
                  const float* __restrict__ b2, float* __restrict__ h2)
{
    __shared__ __nv_bfloat16 As[2][256][G2_ASTR];
    __shared__ __nv_bfloat16 Bs[NCLASS][G2_BSTR];

    const int tid  = threadIdx.x;
    const int warp = tid >> 5;
    const int lane = tid & 31;
    const int grp  = lane >> 2;
    const int tig  = lane & 3;

    const int r0 = blockIdx.x * 256;

    const uint32_t sA = (uint32_t)__cvta_generic_to_shared(&As[0][0][0]);
    const uint32_t ABUF = 256u * G2_ASTR * 2u;

    #pragma unroll
    for (int i = 0; i < 10; i++) {
        int c = tid + i * 128;
        int n = c >> 5;
        int ks = (c & 31) * 8;
        *(uint4*)&Bs[n][ks] = *(const uint4*)&w2t[(size_t)n * NHID + ks];
    }

    float acc[4][5][4];
    #pragma unroll
    for (int i = 0; i < 4; i++)
        #pragma unroll
        for (int j = 0; j < 5; j++)
            #pragma unroll
            for (int r = 0; r < 4; r++) acc[i][j][r] = 0.f;

    const int NT = NHID / 16;   // 16
    auto load_tile = [&](int kt, int b) {
        const uint32_t ab = sA + (uint32_t)b * ABUF;
        #pragma unroll
        for (int i = 0; i < 4; i++) {
            int c = tid + i * 128;
            int row = c >> 1;
            int seg = (c & 1) * 8;
            int gr = min(r0 + row, N_NODES - 1);
            cp_async16(ab + (uint32_t)((row * G2_ASTR + seg) * 2),
                       hb + (size_t)gr * NHID + kt * 16 + seg);
        }
    };

    load_tile(0, 0);
    cp_commit();
    __syncthreads();

    for (int kt = 0; kt < NT; kt++) {
        if (kt + 1 < NT) load_tile(kt + 1, (kt + 1) & 1);
        cp_commit();
        cp_wait1();
        __syncthreads();

        const int buf = kt & 1;
        uint32_t a[4][4], b[5][2];
        #pragma unroll
        for (int mf = 0; mf < 4; mf++) {
            const int r = warp * 64 + mf * 16 + grp;
            a[mf][0] = *(const uint32_t*)&As[buf][r    ][tig * 2    ];
            a[mf][1] = *(const uint32_t*)&As[buf][r + 8][tig * 2    ];
            a[mf][2] = *(const uint32_t*)&As[buf][r    ][tig * 2 + 8];
            a[mf][3] = *(const uint32_t*)&As[buf][r + 8][tig * 2 + 8];
        }
        #pragma unroll
        for (int nf = 0; nf < 5; nf++) {
            const int cn = nf * 8 + grp;
            b[nf][0] = *(const uint32_t*)&Bs[cn][kt * 16 + tig * 2    ];
            b[nf][1] = *(const uint32_t*)&Bs[cn][kt * 16 + tig * 2 + 8];
        }
        #pragma unroll
        for (int mf = 0; mf < 4; mf++)
            #pragma unroll
            for (int nf = 0; nf < 5; nf++) {
                asm volatile(
                    "mma.sync.aligned.m16n8k16.row.col.f32.bf16.bf16.f32 "
                    "{%0,%1,%2,%3}, {%4,%5,%6,%7}, {%8,%9}, {%0,%1,%2,%3};\n"
                    : "+f"(acc[mf][nf][0]), "+f"(acc[mf][nf][1]),
                      "+f"(acc[mf][nf][2]), "+f"(acc[mf][nf][3])
                    : "r"(a[mf][0]), "r"(a[mf][1]), "r"(a[mf][2]), "r"(a[mf][3]),
                      "r"(b[nf][0]), "r"(b[nf][1]));
            }
        __syncthreads();
    }

    #pragma unroll
    for (int nf = 0; nf < 5; nf++) {
        const int col = nf * 8 + 2 * tig;
        const float bx = b2[col], by = b2[col + 1];
        #pragma unroll
        for (int mf = 0; mf < 4; mf++) {
            const int rg = r0 + warp * 64 + mf * 16 + grp;
            if (rg < N_NODES) {
                float2 o;
                o.x = acc[mf][nf][0] + bx;
                o.y = acc[mf][nf][1] + by;
                *(float2*)&h2[(size_t)rg * NCLASS + col] = o;
            }
            if (rg + 8 < N_NODES) {
                float2 o;
                o.x = acc[mf][nf][2] + bx;
                o.y = acc[mf][nf][3] + by;
                *(float2*)&h2[(size_t)(rg + 8) * NCLASS + col] = o;
            }
        }
    }
}

// ================= CSR build (by dst), full-chip 3-phase scan ================
__global__ void __launch_bounds__(256)
zero_deg_kernel(int* __restrict__ deg)
{
    int i = blockIdx.x * 256 + threadIdx.x;
    if (i < N_NODES) deg[i] = 0;
}

__global__ void __launch_bounds__(256)
hist_kernel(const int* __restrict__ edst, int* __restrict__ deg)
{
    int e = blockIdx.x * 256 + threadIdx.x;
    if (e < NEDGE) atomicAdd(&deg[edst[e]], 1);
}

// phase 1: per-block sums of 256 deg entries (coalesced, full chip)
__global__ void __launch_bounds__(256)
partial_kernel(const int* __restrict__ deg, int* __restrict__ bpart)
{
    __shared__ int red[256];
    const int tid = threadIdx.x;
    const int i = blockIdx.x * 256 + tid;
    red[tid] = (i < N_NODES) ? deg[i] : 0;
    __syncthreads();
    #pragma unroll
    for (int off = 128; off > 0; off >>= 1) {
        if (tid < off) red[tid] += red[tid + off];
        __syncthreads();
    }
    if (tid == 0) bpart[blockIdx.x] = red[0];
}

// phase 2: single small block scans the 391 partials -> exclusive block offsets
__global__ void __launch_bounds__(512)
scanpart_kernel(const int* __restrict__ bpart, int* __restrict__ boff)
{
    __shared__ int s[512];
    const int tid = threadIdx.x;
    int v = (tid < NBLK) ? bpart[tid] : 0;
    s[tid] = v;
    __syncthreads();
    for (int off = 1; off < 512; off <<= 1) {
        int t = (tid >= off) ? s[tid - off] : 0;
        __syncthreads();
        s[tid] += t;
        __syncthreads();
    }
    if (tid < NBLK) boff[tid] = s[tid] - v;   // exclusive
}

// phase 3: block-local exclusive scan + offset -> rowptr & cursor (coalesced)
__global__ void __launch_bounds__(256)
rowptr_kernel(const int* __restrict__ deg, const int* __restrict__ boff,
              int* __restrict__ rowptr, int* __restrict__ cursor)
{
    __shared__ int s[256];
    const int tid = threadIdx.x;
    const int i = blockIdx.x * 256 + tid;
    int v = (i < N_NODES) ? deg[i] : 0;
    s[tid] = v;
    __syncthreads();
    for (int off = 1; off < 256; off <<= 1) {
        int t = (tid >= off) ? s[tid - off] : 0;
        __syncthreads();
        s[tid] += t;
        __syncthreads();
    }
    const int base = boff[blockIdx.x];
    if (i < N_NODES) {
        int excl = base + s[tid] - v;
        rowptr[i] = excl;
        cursor[i] = excl;
        if (i == N_NODES - 1) rowptr[N_NODES] = excl + v;
    }
}

__global__ void __launch_bounds__(256)
scatter_kernel(const int* __restrict__ esrc, const int* __restrict__ edst,
               const float* __restrict__ eval_, int* __restrict__ cursor,
               int2* __restrict__ cedge)
{
    int e = blockIdx.x * 256 + threadIdx.x;
    if (e < NEDGE) {
        int d = edst[e];
        int slot = atomicAdd(&cursor[d], 1);
        cedge[slot] = make_int2(esrc[e],
                                __float_as_int((1.0f - ALPHA_F) * eval_[e]));
    }
}

// ======== propagation hop: zout[dst] = alpha*h2[dst] + sum ev*zin[src] =======
__global__ void __launch_bounds__(256)
prop_kernel(const int* __restrict__ rowptr, const int2* __restrict__ cedge,
            const float* __restrict__ h2,
            const float* __restrict__ zin, float* __restrict__ zout)
{
    int idx = blockIdx.x * 256 + threadIdx.x;
    if (idx >= N_NODES * 10) return;
    int dst = idx / 10;
    int g = idx - dst * 10;
    const int col = g * 4;

    int e  = rowptr[dst];
    int e1 = rowptr[dst + 1];

    float4 hv = *(const float4*)&h2[(size_t)dst * NCLASS + col];
    float4 acc0 = make_float4(ALPHA_F * hv.x, ALPHA_F * hv.y,
                              ALPHA_F * hv.z, ALPHA_F * hv.w);
    float4 acc1 = make_float4(0.f, 0.f, 0.f, 0.f);

    for (; e + 4 <= e1; e += 4) {
        int2 d0 = cedge[e], d1 = cedge[e + 1], d2 = cedge[e + 2], d3 = cedge[e + 3];
        float v0 = __int_as_float(d0.y), v1 = __int_as_float(d1.y);
        float v2 = __int_as_float(d2.y), v3 = __int_as_float(d3.y);
        float4 z0 = __ldg((const float4*)&zin[(size_t)d0.x * NCLASS + col]);
        float4 z1 = __ldg((const float4*)&zin[(size_t)d1.x * NCLASS + col]);
        float4 z2 = __ldg((const float4*)&zin[(size_t)d2.x * NCLASS + col]);
        float4 z3 = __ldg((const float4*)&zin[(size_t)d3.x * NCLASS + col]);
        acc0.x = fmaf(v0, z0.x, acc0.x); acc0.y = fmaf(v0, z0.y, acc0.y);
        acc0.z = fmaf(v0, z0.z, acc0.z); acc0.w = fmaf(v0, z0.w, acc0.w);
        acc1.x = fmaf(v1, z1.x, acc1.x); acc1.y = fmaf(v1, z1.y, acc1.y);
        acc1.z = fmaf(v1, z1.z, acc1.z); acc1.w = fmaf(v1, z1.w, acc1.w);
        acc0.x = fmaf(v2, z2.x, acc0.x); acc0.y = fmaf(v2, z2.y, acc0.y);
        acc0.z = fmaf(v2, z2.z, acc0.z); acc0.w = fmaf(v2, z2.w, acc0.w);
        acc1.x = fmaf(v3, z3.x, acc1.x); acc1.y = fmaf(v3, z3.y, acc1.y);
        acc1.z = fmaf(v3, z3.z, acc1.z); acc1.w = fmaf(v3, z3.w, acc1.w);
    }
    for (; e < e1; e++) {
        int2 d0 = cedge[e];
        float v0 = __int_as_float(d0.y);
        float4 z0 = __ldg((const float4*)&zin[(size_t)d0.x * NCLASS + col]);
        acc0.x = fmaf(v0, z0.x, acc0.x); acc0.y = fmaf(v0, z0.y, acc0.y);
        acc0.z = fmaf(v0, z0.z, acc0.z); acc0.w = fmaf(v0, z0.w, acc0.w);
    }
    acc0.x += acc1.x; acc0.y += acc1.y; acc0.z += acc1.z; acc0.w += acc1.w;
    *(float4*)&zout[(size_t)dst * NCLASS + col] = acc0;
}

// ---------------- log_softmax per row ----------------
__global__ void __launch_bounds__(256)
softmax_kernel(const float* __restrict__ z, float* __restrict__ out)
{
    int row = blockIdx.x * 8 + (threadIdx.x >> 5);
    int lane = threadIdx.x & 31;
    if (row >= N_NODES) return;
    const float* zr = z + (size_t)row * NCLASS;
    float v0 = zr[lane];
    bool has2 = (lane + 32) < NCLASS;
    float v1 = has2 ? zr[lane + 32] : -3.402823466e38f;
    float m = fmaxf(v0, v1);
    #pragma unroll
    for (int o = 16; o > 0; o >>= 1) m = fmaxf(m, __shfl_xor_sync(0xffffffffu, m, o));
    float s = __expf(v0 - m) + (has2 ? __expf(v1 - m) : 0.f);
    #pragma unroll
    for (int o = 16; o > 0; o >>= 1) s += __shfl_xor_sync(0xffffffffu, s, o);
    float lse = m + __logf(s);
    float* orow = out + (size_t)row * NCLASS;
    orow[lane] = v0 - lse;
    if (has2) orow[lane + 32] = v1 - lse;
}

// ---------------- launch ----------------
extern "C" void kernel_launch(void* const* d_in, const int* in_sizes, int n_in,
                              void* d_out, int out_size)
{
    const float* x     = (const float*)d_in[0];
    const int*   esrc  = (const int*)  d_in[1];
    const int*   edst  = (const int*)  d_in[2];
    const float* eval_ = (const float*)d_in[3];
    const float* W1    = (const float*)d_in[4];
    const float* b1    = (const float*)d_in[5];
    const float* W2    = (const float*)d_in[6];
    const float* b2    = (const float*)d_in[7];
    float* out = (float*)d_out;

    float *h2, *za;
    __nv_bfloat16 *hb, *xb, *w1b, *w2t;
    int *deg, *rowptr, *cursor, *bpart, *boff;
    int2 *cedge;
    cudaGetSymbolAddress((void**)&hb,     g_hb);
    cudaGetSymbolAddress((void**)&h2,     g_h2);
    cudaGetSymbolAddress((void**)&za,     g_za);
    cudaGetSymbolAddress((void**)&xb,     g_xb);
    cudaGetSymbolAddress((void**)&w1b,    g_w1b);
    cudaGetSymbolAddress((void**)&w2t,    g_w2t);
    cudaGetSymbolAddress((void**)&deg,    g_deg);
    cudaGetSymbolAddress((void**)&rowptr, g_rowptr);
    cudaGetSymbolAddress((void**)&cursor, g_cursor);
    cudaGetSymbolAddress((void**)&bpart,  g_bpart);
    cudaGetSymbolAddress((void**)&boff,   g_boff);
    cudaGetSymbolAddress((void**)&cedge,  g_cedge);

    // bf16 conversions
    conv_x_kernel<<<(N_NODES * NFEAT / 8 + 255) / 256, 256>>>(x, xb);
    conv_w1_kernel<<<(NHID * NFEAT + 255) / 256, 256>>>(W1, w1b);
    conv_w2_kernel<<<(NCLASS * NHID + 255) / 256, 256>>>(W2, w2t);

    // GEMM1 (bf16 mma.sync + ldmatrix) -> hb (bf16)
    dim3 g1((N_NODES + 127) / 128, NHID / 128);   // (782, 2)
    gemm1_bf16_kernel<<<g1, 256>>>(xb, w1b, b1, hb);

    // GEMM2 (bf16 mma.sync) -> h2 (fp32)
    gemm2_bf16_kernel<<<(N_NODES + 255) / 256, 128>>>(hb, w2t, b2, h2);

    // CSR build (full-chip scan)
    zero_deg_kernel<<<NBLK, 256>>>(deg);
    hist_kernel<<<(NEDGE + 255) / 256, 256>>>(edst, deg);
    partial_kernel<<<NBLK, 256>>>(deg, bpart);
    scanpart_kernel<<<1, 512>>>(bpart, boff);
    rowptr_kernel<<<NBLK, 256>>>(deg, boff, rowptr, cursor);
    scatter_kernel<<<(NEDGE + 255) / 256, 256>>>(esrc, edst, eval_, cursor, cedge);

    const int prop_blocks = (N_NODES * 10 + 255) / 256;
    const float* zin = h2;
    for (int i = 0; i < KHOPS; i++) {
        float* zout = (i % 2 == 0) ? za : out;   // last iter (i=9) writes `out`
        prop_kernel<<<prop_blocks, 256>>>(rowptr, cedge, h2, zin, zout);
        zin = zout;
    }

    softmax_kernel<<<(N_NODES + 7) / 8, 256>>>(out, out);
}

// round 13
// speedup vs baseline: 2.4699x; 1.0718x over previous
#include <cuda_runtime.h>
#include <cuda_bf16.h>
#include <cuda_fp16.h>
#include <cstdint>
#include <math.h>

#define N_NODES 100000
#define NFEAT   512
#define NHID    256
#define NCLASS  40
#define NEDGE   1600000
#define KHOPS   10
#define ALPHA_F 0.1f
#define NBLK    391   // ceil(100000/256)

// ---------------- scratch (device globals; no allocs allowed) ----------------
__device__ __nv_bfloat16  g_hb [(size_t)N_NODES * NHID];   // 51.2 MB (bf16 h)
__device__ float          g_h2 [(size_t)N_NODES * NCLASS]; // 16 MB
__device__ __half         g_zha[(size_t)N_NODES * NCLASS]; // 8 MB (fp16 z ping)
__device__ __half         g_zhb[(size_t)N_NODES * NCLASS]; // 8 MB (fp16 z pong)
__device__ __nv_bfloat16  g_xb [(size_t)N_NODES * NFEAT];  // 102.4 MB (bf16 x)
__device__ __nv_bfloat16  g_w1b[(size_t)NHID * NFEAT];     // 256 KB (W1^T bf16 [N][K])
__device__ __nv_bfloat16  g_w2t[(size_t)NCLASS * NHID];    // 20 KB (W2^T bf16 [N][K])
__device__ int   g_deg[N_NODES];
__device__ int   g_rowptr[N_NODES + 1];
__device__ int   g_cursor[N_NODES];
__device__ int   g_bpart[512];
__device__ int   g_boff[512];
__device__ int2  g_cedge[NEDGE];                           // 12.8 MB {src, val bits}

// ---------------- cp.async helpers ----------------
__device__ __forceinline__ void cp_async16(uint32_t saddr, const void* gaddr) {
    asm volatile("cp.async.cg.shared.global [%0], [%1], 16;\n" :: "r"(saddr), "l"(gaddr));
}
__device__ __forceinline__ void cp_commit() {
    asm volatile("cp.async.commit_group;\n" ::: "memory");
}
__device__ __forceinline__ void cp_wait1() {
    asm volatile("cp.async.wait_group 1;\n" ::: "memory");
}
__device__ __forceinline__ void ldsm_x4(uint32_t& r0, uint32_t& r1, uint32_t& r2,
                                        uint32_t& r3, uint32_t addr) {
    asm volatile("ldmatrix.sync.aligned.m8n8.x4.shared.b16 {%0,%1,%2,%3}, [%4];"
                 : "=r"(r0), "=r"(r1), "=r"(r2), "=r"(r3) : "r"(addr));
}

// ---------------- bf16 conversions ----------------
__global__ void __launch_bounds__(256)
conv_x_kernel(const float* __restrict__ x, __nv_bfloat16* __restrict__ xb)
{
    int i = blockIdx.x * 256 + threadIdx.x;         // per 8 floats
    const int n8 = N_NODES * NFEAT / 8;
    if (i < n8) {
        float4 a = ((const float4*)x)[2 * i];
        float4 b = ((const float4*)x)[2 * i + 1];
        __nv_bfloat162 p0 = __floats2bfloat162_rn(a.x, a.y);
        __nv_bfloat162 p1 = __floats2bfloat162_rn(a.z, a.w);
        __nv_bfloat162 p2 = __floats2bfloat162_rn(b.x, b.y);
        __nv_bfloat162 p3 = __floats2bfloat162_rn(b.z, b.w);
        uint4 o;
        o.x = *reinterpret_cast<unsigned*>(&p0);
        o.y = *reinterpret_cast<unsigned*>(&p1);
        o.z = *reinterpret_cast<unsigned*>(&p2);
        o.w = *reinterpret_cast<unsigned*>(&p3);
        ((uint4*)xb)[i] = o;
    }
}

__global__ void __launch_bounds__(256)
conv_w1_kernel(const float* __restrict__ W1, __nv_bfloat16* __restrict__ w1b)
{
    int id = blockIdx.x * 256 + threadIdx.x;        // (n,k), k fast
    if (id < NHID * NFEAT) {
        int n = id >> 9;
        int k = id & 511;
        w1b[id] = __float2bfloat16(W1[(size_t)k * NHID + n]);
    }
}

__global__ void __launch_bounds__(256)
conv_w2_kernel(const float* __restrict__ W2, __nv_bfloat16* __restrict__ w2t)
{
    int id = blockIdx.x * 256 + threadIdx.x;        // (n,k), k fast
    if (id < NCLASS * NHID) {
        int n = id >> 8;
        int k = id & 255;
        w2t[id] = __float2bfloat16(W2[(size_t)k * NCLASS + n]);
    }
}

// ---------------- GEMM1: hb = relu(x @ W1 + b1) via bf16 mma.sync + ldmatrix -
#define G1_BK  32
#define G1_STR 40

__global__ void __launch_bounds__(256, 2)
gemm1_bf16_kernel(const __nv_bfloat16* __restrict__ xb,
                  const __nv_bfloat16* __restrict__ w1b,
                  const float* __restrict__ b1, __nv_bfloat16* __restrict__ hb)
{
    __shared__ __nv_bfloat16 As[2][128][G1_STR];
    __shared__ __nv_bfloat16 Bs[2][128][G1_STR];

    const int tid  = threadIdx.x;
    const int warp = tid >> 5;
    const int lane = tid & 31;
    const int grp  = lane >> 2;
    const int tig  = lane & 3;
    const int warp_m = warp & 1;
    const int warp_n = warp >> 1;

    const int m0 = blockIdx.x * 128;
    const int n0 = blockIdx.y * 128;

    const uint32_t sA = (uint32_t)__cvta_generic_to_shared(&As[0][0][0]);
    const uint32_t sB = (uint32_t)__cvta_generic_to_shared(&Bs[0][0][0]);
    const uint32_t BUFB = 128u * G1_STR * 2u;

    const int lm_row = lane & 15;
    const int lm_kof = (lane >> 4) * 8;

    float acc[4][4][4];
    #pragma unroll
    for (int i = 0; i < 4; i++)
        #pragma unroll
        for (int j = 0; j < 4; j++)
            #pragma unroll
            for (int r = 0; r < 4; r++) acc[i][j][r] = 0.f;

    const int c0 = tid, c1 = tid + 256;
    const int ar0 = c0 >> 2, ak0 = (c0 & 3) * 8;
    const int ar1 = c1 >> 2, ak1 = (c1 & 3) * 8;
    const int gr0 = min(m0 + ar0, N_NODES - 1);
    const int gr1 = min(m0 + ar1, N_NODES - 1);

    const int NT = NFEAT / G1_BK;  // 16

    auto load_tile = [&](int kt, int b) {
        const int kb = kt * G1_BK;
        const uint32_t ab = sA + (uint32_t)b * BUFB;
        const uint32_t bb = sB + (uint32_t)b * BUFB;
        cp_async16(ab + (uint32_t)((ar0 * G1_STR + ak0) * 2),
                   xb + (size_t)gr0 * NFEAT + kb + ak0);
        cp_async16(ab + (uint32_t)((ar1 * G1_STR + ak1) * 2),
                   xb + (size_t)gr1 * NFEAT + kb + ak1);
        cp_async16(bb + (uint32_t)((ar0 * G1_STR + ak0) * 2),
                   w1b + (size_t)(n0 + ar0) * NFEAT + kb + ak0);
        cp_async16(bb + (uint32_t)((ar1 * G1_STR + ak1) * 2),
                   w1b + (size_t)(n0 + ar1) * NFEAT + kb + ak1);
    };

    load_tile(0, 0);
    cp_commit();

    for (int kt = 0; kt < NT; kt++) {
        if (kt + 1 < NT) load_tile(kt + 1, (kt + 1) & 1);
        cp_commit();
        cp_wait1();
        __syncthreads();

        const int buf = kt & 1;
        const uint32_t abuf = sA + (uint32_t)buf * BUFB;
        const uint32_t bbuf = sB + (uint32_t)buf * BUFB;
        #pragma unroll
        for (int ks = 0; ks < 2; ks++) {
            const int kb = ks * 16 + lm_kof;
            uint32_t a[4][4], b[4][2];
            #pragma unroll
            for (int mf = 0; mf < 4; mf++) {
                const int r = warp_m * 64 + mf * 16 + lm_row;
                ldsm_x4(a[mf][0], a[mf][1], a[mf][2], a[mf][3],
                        abuf + (uint32_t)((r * G1_STR + kb) * 2));
            }
            #pragma unroll
            for (int np = 0; np < 2; np++) {
                const int cn = warp_n * 32 + np * 16 + lm_row;
                ldsm_x4(b[2*np][0], b[2*np + 1][0], b[2*np][1], b[2*np + 1][1],
                        bbuf + (uint32_t)((cn * G1_STR + kb) * 2));
            }
            #pragma unroll
            for (int mf = 0; mf < 4; mf++)
                #pragma unroll
                for (int nf = 0; nf < 4; nf++) {
                    asm volatile(
                        "mma.sync.aligned.m16n8k16.row.col.f32.bf16.bf16.f32 "
                        "{%0,%1,%2,%3}, {%4,%5,%6,%7}, {%8,%9}, {%0,%1,%2,%3};\n"
                        : "+f"(acc[mf][nf][0]), "+f"(acc[mf][nf][1]),
                          "+f"(acc[mf][nf][2]), "+f"(acc[mf][nf][3])
                        : "r"(a[mf][0]), "r"(a[mf][1]), "r"(a[mf][2]), "r"(a[mf][3]),
                          "r"(b[nf][0]), "r"(b[nf][1]));
                }
        }
        __syncthreads();
    }

    #pragma unroll
    for (int nf = 0; nf < 4; nf++) {
        const int cg = n0 + warp_n * 32 + nf * 8 + 2 * tig;
        const float bx = b1[cg], by = b1[cg + 1];
        #pragma unroll
        for (int mf = 0; mf < 4; mf++) {
            const int rg = m0 + warp_m * 64 + mf * 16 + grp;
            if (rg < N_NODES) {
                __nv_bfloat162 o = __floats2bfloat162_rn(
                    fmaxf(acc[mf][nf][0] + bx, 0.f),
                    fmaxf(acc[mf][nf][1] + by, 0.f));
                *(uint32_t*)&hb[(size_t)rg * NHID + cg] = *reinterpret_cast<uint32_t*>(&o);
            }
            if (rg + 8 < N_NODES) {
                __nv_bfloat162 o = __floats2bfloat162_rn(
                    fmaxf(acc[mf][nf][2] + bx, 0.f),
                    fmaxf(acc[mf][nf][3] + by, 0.f));
                *(uint32_t*)&hb[(size_t)(rg + 8) * NHID + cg] = *reinterpret_cast<uint32_t*>(&o);
            }
        }
    }
}

// ---------------- GEMM2: h2 = hb @ W2 + b2 via bf16 mma.sync -----------------
#define G2_ASTR 24
#define G2_BSTR 264

__global__ void __launch_bounds__(128)
gemm2_bf16_kernel(const __nv_bfloat16* __restrict__ hb,
                  const __nv_bfloat16* __restrict__ w2t,
                  const float* __restrict__ b2, float* __restrict__ h2)
{
    __shared__ __nv_bfloat16 As[2][256][G2_ASTR];
    __shared__ __nv_bfloat16 Bs[NCLASS][G2_BSTR];

    const int tid  = threadIdx.x;
    const int warp = tid >> 5;
    const int lane = tid & 31;
    const int grp  = lane >> 2;
    const int tig  = lane & 3;

    const int r0 = blockIdx.x * 256;

    const uint32_t sA = (uint32_t)__cvta_generic_to_shared(&As[0][0][0]);
    const uint32_t ABUF = 256u * G2_ASTR * 2u;

    #pragma unroll
    for (int i = 0; i < 10; i++) {
        int c = tid + i * 128;
        int n = c >> 5;
        int ks = (c & 31) * 8;
        *(uint4*)&Bs[n][ks] = *(const uint4*)&w2t[(size_t)n * NHID + ks];
    }

    float acc[4][5][4];
    #pragma unroll
    for (int i = 0; i < 4; i++)
        #pragma unroll
        for (int j = 0; j < 5; j++)
            #pragma unroll
            for (int r = 0; r < 4; r++) acc[i][j][r] = 0.f;

    const int NT = NHID / 16;   // 16
    auto load_tile = [&](int kt, int b) {
        const uint32_t ab = sA + (uint32_t)b * ABUF;
        #pragma unroll
        for (int i = 0; i < 4; i++) {
            int c = tid + i * 128;
            int row = c >> 1;
            int seg = (c & 1) * 8;
            int gr = min(r0 + row, N_NODES - 1);
            cp_async16(ab + (uint32_t)((row * G2_ASTR + seg) * 2),
                       hb + (size_t)gr * NHID + kt * 16 + seg);
        }
    };

    load_tile(0, 0);
    cp_commit();
    __syncthreads();

    for (int kt = 0; kt < NT; kt++) {
        if (kt + 1 < NT) load_tile(kt + 1, (kt + 1) & 1);
        cp_commit();
        cp_wait1();
        __syncthreads();

        const int buf = kt & 1;
        uint32_t a[4][4], b[5][2];
        #pragma unroll
        for (int mf = 0; mf < 4; mf++) {
            const int r = warp * 64 + mf * 16 + grp;
            a[mf][0] = *(const uint32_t*)&As[buf][r    ][tig * 2    ];
            a[mf][1] = *(const uint32_t*)&As[buf][r + 8][tig * 2    ];
            a[mf][2] = *(const uint32_t*)&As[buf][r    ][tig * 2 + 8];
            a[mf][3] = *(const uint32_t*)&As[buf][r + 8][tig * 2 + 8];
        }
        #pragma unroll
        for (int nf = 0; nf < 5; nf++) {
            const int cn = nf * 8 + grp;
            b[nf][0] = *(const uint32_t*)&Bs[cn][kt * 16 + tig * 2    ];
            b[nf][1] = *(const uint32_t*)&Bs[cn][kt * 16 + tig * 2 + 8];
        }
        #pragma unroll
        for (int mf = 0; mf < 4; mf++)
            #pragma unroll
            for (int nf = 0; nf < 5; nf++) {
                asm volatile(
                    "mma.sync.aligned.m16n8k16.row.col.f32.bf16.bf16.f32 "
                    "{%0,%1,%2,%3}, {%4,%5,%6,%7}, {%8,%9}, {%0,%1,%2,%3};\n"
                    : "+f"(acc[mf][nf][0]), "+f"(acc[mf][nf][1]),
                      "+f"(acc[mf][nf][2]), "+f"(acc[mf][nf][3])
                    : "r"(a[mf][0]), "r"(a[mf][1]), "r"(a[mf][2]), "r"(a[mf][3]),
                      "r"(b[nf][0]), "r"(b[nf][1]));
            }
        __syncthreads();
    }

    #pragma unroll
    for (int nf = 0; nf < 5; nf++) {
        const int col = nf * 8 + 2 * tig;
        const float bx = b2[col], by = b2[col + 1];
        #pragma unroll
        for (int mf = 0; mf < 4; mf++) {
            const int rg = r0 + warp * 64 + mf * 16 + grp;
            if (rg < N_NODES) {
                float2 o;
                o.x = acc[mf][nf][0] + bx;
                o.y = acc[mf][nf][1] + by;
                *(float2*)&h2[(size_t)rg * NCLASS + col] = o;
            }
            if (rg + 8 < N_NODES) {
                float2 o;
                o.x = acc[mf][nf][2] + bx;
                o.y = acc[mf][nf][3] + by;
                *(float2*)&h2[(size_t)(rg + 8) * NCLASS + col] = o;
            }
        }
    }
}

// ================= CSR build (by dst), full-chip 3-phase scan ================
__global__ void __launch_bounds__(256)
zero_deg_kernel(int* __restrict__ deg)
{
    int i = blockIdx.x * 256 + threadIdx.x;
    if (i < N_NODES) deg[i] = 0;
}

__global__ void __launch_bounds__(256)
hist_kernel(const int* __restrict__ edst, int* __restrict__ deg)
{
    int e = blockIdx.x * 256 + threadIdx.x;
    if (e < NEDGE) atomicAdd(&deg[edst[e]], 1);
}

__global__ void __launch_bounds__(256)
partial_kernel(const int* __restrict__ deg, int* __restrict__ bpart)
{
    __shared__ int red[256];
    const int tid = threadIdx.x;
    const int i = blockIdx.x * 256 + tid;
    red[tid] = (i < N_NODES) ? deg[i] : 0;
    __syncthreads();
    #pragma unroll
    for (int off = 128; off > 0; off >>= 1) {
        if (tid < off) red[tid] += red[tid + off];
        __syncthreads();
    }
    if (tid == 0) bpart[blockIdx.x] = red[0];
}

__global__ void __launch_bounds__(512)
scanpart_kernel(const int* __restrict__ bpart, int* __restrict__ boff)
{
    __shared__ int s[512];
    const int tid = threadIdx.x;
    int v = (tid < NBLK) ? bpart[tid] : 0;
    s[tid] = v;
    __syncthreads();
    for (int off = 1; off < 512; off <<= 1) {
        int t = (tid >= off) ? s[tid - off] : 0;
        __syncthreads();
        s[tid] += t;
        __syncthreads();
    }
    if (tid < NBLK) boff[tid] = s[tid] - v;   // exclusive
}

__global__ void __launch_bounds__(256)
rowptr_kernel(const int* __restrict__ deg, const int* __restrict__ boff,
              int* __restrict__ rowptr, int* __restrict__ cursor)
{
    __shared__ int s[256];
    const int tid = threadIdx.x;
    const int i = blockIdx.x * 256 + tid;
    int v = (i < N_NODES) ? deg[i] : 0;
    s[tid] = v;
    __syncthreads();
    for (int off = 1; off < 256; off <<= 1) {
        int t = (tid >= off) ? s[tid - off] : 0;
        __syncthreads();
        s[tid] += t;
        __syncthreads();
    }
    const int base = boff[blockIdx.x];
    if (i < N_NODES) {
        int excl = base + s[tid] - v;
        rowptr[i] = excl;
        cursor[i] = excl;
        if (i == N_NODES - 1) rowptr[N_NODES] = excl + v;
    }
}

__global__ void __launch_bounds__(256)
scatter_kernel(const int* __restrict__ esrc, const int* __restrict__ edst,
               const float* __restrict__ eval_, int* __restrict__ cursor,
               int2* __restrict__ cedge)
{
    int e = blockIdx.x * 256 + threadIdx.x;
    if (e < NEDGE) {
        int d = edst[e];
        int slot = atomicAdd(&cursor[d], 1);
        cedge[slot] = make_int2(esrc[e],
                                __float_as_int((1.0f - ALPHA_F) * eval_[e]));
    }
}

// ======== propagation hop: zout[dst] = alpha*h2[dst] + sum ev*zin[src] =======
// IN16/OUT16 select fp16 vs fp32 for the z iterate; accumulation always fp32.
template<int IN16, int OUT16>
__global__ void __launch_bounds__(256)
prop_kernel(const int* __restrict__ rowptr, const int2* __restrict__ cedge,
            const float* __restrict__ h2,
            const void* __restrict__ zin_, void* __restrict__ zout_)
{
    int idx = blockIdx.x * 256 + threadIdx.x;
    if (idx >= N_NODES * 10) return;
    int dst = idx / 10;
    int g = idx - dst * 10;
    const int col = g * 4;

    int e  = rowptr[dst];
    int e1 = rowptr[dst + 1];

    auto loadz = [&](int src) -> float4 {
        if (IN16) {
            const __half* z = (const __half*)zin_ + (size_t)src * NCLASS + col;
            uint2 r = __ldg((const uint2*)z);
            __half2 h0 = *reinterpret_cast<__half2*>(&r.x);
            __half2 h1 = *reinterpret_cast<__half2*>(&r.y);
            float2 f0 = __half22float2(h0);
            float2 f1 = __half22float2(h1);
            return make_float4(f0.x, f0.y, f1.x, f1.y);
        } else {
            return __ldg((const float4*)((const float*)zin_ + (size_t)src * NCLASS + col));
        }
    };

    float4 hv = *(const float4*)&h2[(size_t)dst * NCLASS + col];
    float4 acc0 = make_float4(ALPHA_F * hv.x, ALPHA_F * hv.y,
                              ALPHA_F * hv.z, ALPHA_F * hv.w);
    float4 acc1 = make_float4(0.f, 0.f, 0.f, 0.f);

    for (; e + 4 <= e1; e += 4) {
        int2 d0 = cedge[e], d1 = cedge[e + 1], d2 = cedge[e + 2], d3 = cedge[e + 3];
        float v0 = __int_as_float(d0.y), v1 = __int_as_float(d1.y);
        float v2 = __int_as_float(d2.y), v3 = __int_as_float(d3.y);
        float4 z0 = loadz(d0.x);
        float4 z1 = loadz(d1.x);
        float4 z2 = loadz(d2.x);
        float4 z3 = loadz(d3.x);
        acc0.x = fmaf(v0, z0.x, acc0.x); acc0.y = fmaf(v0, z0.y, acc0.y);
        acc0.z = fmaf(v0, z0.z, acc0.z); acc0.w = fmaf(v0, z0.w, acc0.w);
        acc1.x = fmaf(v1, z1.x, acc1.x); acc1.y = fmaf(v1, z1.y, acc1.y);
        acc1.z = fmaf(v1, z1.z, acc1.z); acc1.w = fmaf(v1, z1.w, acc1.w);
        acc0.x = fmaf(v2, z2.x, acc0.x); acc0.y = fmaf(v2, z2.y, acc0.y);
        acc0.z = fmaf(v2, z2.z, acc0.z); acc0.w = fmaf(v2, z2.w, acc0.w);
        acc1.x = fmaf(v3, z3.x, acc1.x); acc1.y = fmaf(v3, z3.y, acc1.y);
        acc1.z = fmaf(v3, z3.z, acc1.z); acc1.w = fmaf(v3, z3.w, acc1.w);
    }
    for (; e < e1; e++) {
        int2 d0 = cedge[e];
        float v0 = __int_as_float(d0.y);
        float4 z0 = loadz(d0.x);
        acc0.x = fmaf(v0, z0.x, acc0.x); acc0.y = fmaf(v0, z0.y, acc0.y);
        acc0.z = fmaf(v0, z0.z, acc0.z); acc0.w = fmaf(v0, z0.w, acc0.w);
    }
    acc0.x += acc1.x; acc0.y += acc1.y; acc0.z += acc1.z; acc0.w += acc1.w;

    if (OUT16) {
        __half2 p0 = __floats2half2_rn(acc0.x, acc0.y);
        __half2 p1 = __floats2half2_rn(acc0.z, acc0.w);
        uint2 o;
        o.x = *reinterpret_cast<uint32_t*>(&p0);
        o.y = *reinterpret_cast<uint32_t*>(&p1);
        *(uint2*)((__half*)zout_ + (size_t)dst * NCLASS + col) = o;
    } else {
        *(float4*)((float*)zout_ + (size_t)dst * NCLASS + col) = acc0;
    }
}

// ---------------- log_softmax per row ----------------
__global__ void __launch_bounds__(256)
softmax_kernel(const float* __restrict__ z, float* __restrict__ out)
{
    int row = blockIdx.x * 8 + (threadIdx.x >> 5);
    int lane = threadIdx.x & 31;
    if (row >= N_NODES) return;
    const float* zr = z + (size_t)row * NCLASS;
    float v0 = zr[lane];
    bool has2 = (lane + 32) < NCLASS;
    float v1 = has2 ? zr[lane + 32] : -3.402823466e38f;
    float m = fmaxf(v0, v1);
    #pragma unroll
    for (int o = 16; o > 0; o >>= 1) m = fmaxf(m, __shfl_xor_sync(0xffffffffu, m, o));
    float s = __expf(v0 - m) + (has2 ? __expf(v1 - m) : 0.f);
    #pragma unroll
    for (int o = 16; o > 0; o >>= 1) s += __shfl_xor_sync(0xffffffffu, s, o);
    float lse = m + __logf(s);
    float* orow = out + (size_t)row * NCLASS;
    orow[lane] = v0 - lse;
    if (has2) orow[lane + 32] = v1 - lse;
}

// ---------------- launch ----------------
extern "C" void kernel_launch(void* const* d_in, const int* in_sizes, int n_in,
                              void* d_out, int out_size)
{
    const float* x     = (const float*)d_in[0];
    const int*   esrc  = (const int*)  d_in[1];
    const int*   edst  = (const int*)  d_in[2];
    const float* eval_ = (const float*)d_in[3];
    const float* W1    = (const float*)d_in[4];
    const float* b1    = (const float*)d_in[5];
    const float* W2    = (const float*)d_in[6];
    const float* b2    = (const float*)d_in[7];
    float* out = (float*)d_out;

    float *h2;
    __half *zha, *zhb;
    __nv_bfloat16 *hb, *xb, *w1b, *w2t;
    int *deg, *rowptr, *cursor, *bpart, *boff;
    int2 *cedge;
    cudaGetSymbolAddress((void**)&hb,     g_hb);
    cudaGetSymbolAddress((void**)&h2,     g_h2);
    cudaGetSymbolAddress((void**)&zha,    g_zha);
    cudaGetSymbolAddress((void**)&zhb,    g_zhb);
    cudaGetSymbolAddress((void**)&xb,     g_xb);
    cudaGetSymbolAddress((void**)&w1b,    g_w1b);
    cudaGetSymbolAddress((void**)&w2t,    g_w2t);
    cudaGetSymbolAddress((void**)&deg,    g_deg);
    cudaGetSymbolAddress((void**)&rowptr, g_rowptr);
    cudaGetSymbolAddress((void**)&cursor, g_cursor);
    cudaGetSymbolAddress((void**)&bpart,  g_bpart);
    cudaGetSymbolAddress((void**)&boff,   g_boff);
    cudaGetSymbolAddress((void**)&cedge,  g_cedge);

    // bf16 conversions
    conv_x_kernel<<<(N_NODES * NFEAT / 8 + 255) / 256, 256>>>(x, xb);
    conv_w1_kernel<<<(NHID * NFEAT + 255) / 256, 256>>>(W1, w1b);
    conv_w2_kernel<<<(NCLASS * NHID + 255) / 256, 256>>>(W2, w2t);

    // GEMM1 (bf16 mma.sync + ldmatrix) -> hb (bf16)
    dim3 g1((N_NODES + 127) / 128, NHID / 128);   // (782, 2)
    gemm1_bf16_kernel<<<g1, 256>>>(xb, w1b, b1, hb);

    // GEMM2 (bf16 mma.sync) -> h2 (fp32)
    gemm2_bf16_kernel<<<(N_NODES + 255) / 256, 128>>>(hb, w2t, b2, h2);

    // CSR build (full-chip scan)
    zero_deg_kernel<<<NBLK, 256>>>(deg);
    hist_kernel<<<(NEDGE + 255) / 256, 256>>>(edst, deg);
    partial_kernel<<<NBLK, 256>>>(deg, bpart);
    scanpart_kernel<<<1, 512>>>(bpart, boff);
    rowptr_kernel<<<NBLK, 256>>>(deg, boff, rowptr, cursor);
    scatter_kernel<<<(NEDGE + 255) / 256, 256>>>(esrc, edst, eval_, cursor, cedge);

    const int prop_blocks = (N_NODES * 10 + 255) / 256;

    // hop 0: fp32 h2 -> fp16 zha
    prop_kernel<0, 1><<<prop_blocks, 256>>>(rowptr, cedge, h2, h2, zha);
    // hops 1..8: fp16 -> fp16 ping-pong
    const __half* zi = zha;
    __half* zo = zhb;
    for (int i = 1; i < KHOPS - 1; i++) {
        prop_kernel<1, 1><<<prop_blocks, 256>>>(rowptr, cedge, h2, zi, zo);
        const __half* t = zo; zo = (__half*)zi; zi = t;
    }
    // hop 9: fp16 -> fp32 out
    prop_kernel<1, 0><<<prop_blocks, 256>>>(rowptr, cedge, h2, zi, out);

    softmax_kernel<<<(N_NODES + 7) / 8, 256>>>(out, out);
}

// round 14
// speedup vs baseline: 2.6429x; 1.0700x over previous
#include <cuda_runtime.h>
#include <cuda_bf16.h>
#include <cuda_fp16.h>
#include <cstdint>
#include <math.h>

#define N_NODES 100000
#define NFEAT   512
#define NHID    256
#define NCLASS  40
#define NEDGE   1600000
#define KHOPS   10
#define ALPHA_F 0.1f
#define NBLK    391   // ceil(100000/256)

// ---------------- scratch (device globals; no allocs allowed) ----------------
__device__ __nv_bfloat16  g_hb [(size_t)N_NODES * NHID];   // 51.2 MB (bf16 h)
__device__ __half         g_h2h[(size_t)N_NODES * NCLASS]; // 8 MB (fp16 h2)
__device__ __half         g_zha[(size_t)N_NODES * NCLASS]; // 8 MB (fp16 z ping)
__device__ __half         g_zhb[(size_t)N_NODES * NCLASS]; // 8 MB (fp16 z pong)
__device__ __nv_bfloat16  g_xb [(size_t)N_NODES * NFEAT];  // 102.4 MB (bf16 x)
__device__ __nv_bfloat16  g_w1b[(size_t)NHID * NFEAT];     // 256 KB (W1^T bf16 [N][K])
__device__ __nv_bfloat16  g_w2t[(size_t)NCLASS * NHID];    // 20 KB (W2^T bf16 [N][K])
__device__ int   g_deg[N_NODES];
__device__ int   g_rowptr[N_NODES + 1];
__device__ int   g_cursor[N_NODES];
__device__ int   g_bpart[512];
__device__ int   g_boff[512];
__device__ int2  g_cedge[NEDGE];                           // 12.8 MB {src, val bits}

// ---------------- cp.async helpers ----------------
__device__ __forceinline__ void cp_async16(uint32_t saddr, const void* gaddr) {
    asm volatile("cp.async.cg.shared.global [%0], [%1], 16;\n" :: "r"(saddr), "l"(gaddr));
}
__device__ __forceinline__ void cp_commit() {
    asm volatile("cp.async.commit_group;\n" ::: "memory");
}
__device__ __forceinline__ void cp_wait1() {
    asm volatile("cp.async.wait_group 1;\n" ::: "memory");
}
__device__ __forceinline__ void ldsm_x4(uint32_t& r0, uint32_t& r1, uint32_t& r2,
                                        uint32_t& r3, uint32_t addr) {
    asm volatile("ldmatrix.sync.aligned.m8n8.x4.shared.b16 {%0,%1,%2,%3}, [%4];"
                 : "=r"(r0), "=r"(r1), "=r"(r2), "=r"(r3) : "r"(addr));
}

// ---------------- bf16 conversions ----------------
__global__ void __launch_bounds__(256)
conv_x_kernel(const float* __restrict__ x, __nv_bfloat16* __restrict__ xb)
{
    int i = blockIdx.x * 256 + threadIdx.x;         // per 8 floats
    const int n8 = N_NODES * NFEAT / 8;
    if (i < n8) {
        float4 a = ((const float4*)x)[2 * i];
        float4 b = ((const float4*)x)[2 * i + 1];
        __nv_bfloat162 p0 = __floats2bfloat162_rn(a.x, a.y);
        __nv_bfloat162 p1 = __floats2bfloat162_rn(a.z, a.w);
        __nv_bfloat162 p2 = __floats2bfloat162_rn(b.x, b.y);
        __nv_bfloat162 p3 = __floats2bfloat162_rn(b.z, b.w);
        uint4 o;
        o.x = *reinterpret_cast<unsigned*>(&p0);
        o.y = *reinterpret_cast<unsigned*>(&p1);
        o.z = *reinterpret_cast<unsigned*>(&p2);
        o.w = *reinterpret_cast<unsigned*>(&p3);
        ((uint4*)xb)[i] = o;
    }
}

__global__ void __launch_bounds__(256)
conv_w1_kernel(const float* __restrict__ W1, __nv_bfloat16* __restrict__ w1b)
{
    int id = blockIdx.x * 256 + threadIdx.x;        // (n,k), k fast
    if (id < NHID * NFEAT) {
        int n = id >> 9;
        int k = id & 511;
        w1b[id] = __float2bfloat16(W1[(size_t)k * NHID + n]);
    }
}

__global__ void __launch_bounds__(256)
conv_w2_kernel(const float* __restrict__ W2, __nv_bfloat16* __restrict__ w2t)
{
    int id = blockIdx.x * 256 + threadIdx.x;        // (n,k), k fast
    if (id < NCLASS * NHID) {
        int n = id >> 8;
        int k = id & 255;
        w2t[id] = __float2bfloat16(W2[(size_t)k * NCLASS + n]);
    }
}

// ---------------- GEMM1: hb = relu(x @ W1 + b1) via bf16 mma.sync + ldmatrix -
#define G1_BK  32
#define G1_STR 40

__global__ void __launch_bounds__(256, 2)
gemm1_bf16_kernel(const __nv_bfloat16* __restrict__ xb,
                  const __nv_bfloat16* __restrict__ w1b,
                  const float* __restrict__ b1, __nv_bfloat16* __restrict__ hb)
{
    __shared__ __nv_bfloat16 As[2][128][G1_STR];
    __shared__ __nv_bfloat16 Bs[2][128][G1_STR];

    const int tid  = threadIdx.x;
    const int warp = tid >> 5;
    const int lane = tid & 31;
    const int grp  = lane >> 2;
    const int tig  = lane & 3;
    const int warp_m = warp & 1;
    const int warp_n = warp >> 1;

    const int m0 = blockIdx.x * 128;
    const int n0 = blockIdx.y * 128;

    const uint32_t sA = (uint32_t)__cvta_generic_to_shared(&As[0][0][0]);
    const uint32_t sB = (uint32_t)__cvta_generic_to_shared(&Bs[0][0][0]);
    const uint32_t BUFB = 128u * G1_STR * 2u;

    const int lm_row = lane & 15;
    const int lm_kof = (lane >> 4) * 8;

    float acc[4][4][4];
    #pragma unroll
    for (int i = 0; i < 4; i++)
        #pragma unroll
        for (int j = 0; j < 4; j++)
            #pragma unroll
            for (int r = 0; r < 4; r++) acc[i][j][r] = 0.f;

    const int c0 = tid, c1 = tid + 256;
    const int ar0 = c0 >> 2, ak0 = (c0 & 3) * 8;
    const int ar1 = c1 >> 2, ak1 = (c1 & 3) * 8;
    const int gr0 = min(m0 + ar0, N_NODES - 1);
    const int gr1 = min(m0 + ar1, N_NODES - 1);

    const int NT = NFEAT / G1_BK;  // 16

    auto load_tile = [&](int kt, int b) {
        const int kb = kt * G1_BK;
        const uint32_t ab = sA + (uint32_t)b * BUFB;
        const uint32_t bb = sB + (uint32_t)b * BUFB;
        cp_async16(ab + (uint32_t)((ar0 * G1_STR + ak0) * 2),
                   xb + (size_t)gr0 * NFEAT + kb + ak0);
        cp_async16(ab + (uint32_t)((ar1 * G1_STR + ak1) * 2),
                   xb + (size_t)gr1 * NFEAT + kb + ak1);
        cp_async16(bb + (uint32_t)((ar0 * G1_STR + ak0) * 2),
                   w1b + (size_t)(n0 + ar0) * NFEAT + kb + ak0);
        cp_async16(bb + (uint32_t)((ar1 * G1_STR + ak1) * 2),
                   w1b + (size_t)(n0 + ar1) * NFEAT + kb + ak1);
    };

    load_tile(0, 0);
    cp_commit();

    for (int kt = 0; kt < NT; kt++) {
        if (kt + 1 < NT) load_tile(kt + 1, (kt + 1) & 1);
        cp_commit();
        cp_wait1();
        __syncthreads();

        const int buf = kt & 1;
        const uint32_t abuf = sA + (uint32_t)buf * BUFB;
        const uint32_t bbuf = sB + (uint32_t)buf * BUFB;
        #pragma unroll
        for (int ks = 0; ks < 2; ks++) {
            const int kb = ks * 16 + lm_kof;
            uint32_t a[4][4], b[4][2];
            #pragma unroll
            for (int mf = 0; mf < 4; mf++) {
                const int r = warp_m * 64 + mf * 16 + lm_row;
                ldsm_x4(a[mf][0], a[mf][1], a[mf][2], a[mf][3],
                        abuf + (uint32_t)((r * G1_STR + kb) * 2));
            }
            #pragma unroll
            for (int np = 0; np < 2; np++) {
                const int cn = warp_n * 32 + np * 16 + lm_row;
                ldsm_x4(b[2*np][0], b[2*np + 1][0], b[2*np][1], b[2*np + 1][1],
                        bbuf + (uint32_t)((cn * G1_STR + kb) * 2));
            }
            #pragma unroll
            for (int mf = 0; mf < 4; mf++)
                #pragma unroll
                for (int nf = 0; nf < 4; nf++) {
                    asm volatile(
                        "mma.sync.aligned.m16n8k16.row.col.f32.bf16.bf16.f32 "
                        "{%0,%1,%2,%3}, {%4,%5,%6,%7}, {%8,%9}, {%0,%1,%2,%3};\n"
                        : "+f"(acc[mf][nf][0]), "+f"(acc[mf][nf][1]),
                          "+f"(acc[mf][nf][2]), "+f"(acc[mf][nf][3])
                        : "r"(a[mf][0]), "r"(a[mf][1]), "r"(a[mf][2]), "r"(a[mf][3]),
                          "r"(b[nf][0]), "r"(b[nf][1]));
                }
        }
        __syncthreads();
    }

    #pragma unroll
    for (int nf = 0; nf < 4; nf++) {
        const int cg = n0 + warp_n * 32 + nf * 8 + 2 * tig;
        const float bx = b1[cg], by = b1[cg + 1];
        #pragma unroll
        for (int mf = 0; mf < 4; mf++) {
            const int rg = m0 + warp_m * 64 + mf * 16 + grp;
            if (rg < N_NODES) {
                __nv_bfloat162 o = __floats2bfloat162_rn(
                    fmaxf(acc[mf][nf][0] + bx, 0.f),
                    fmaxf(acc[mf][nf][1] + by, 0.f));
                *(uint32_t*)&hb[(size_t)rg * NHID + cg] = *reinterpret_cast<uint32_t*>(&o);
            }
            if (rg + 8 < N_NODES) {
                __nv_bfloat162 o = __floats2bfloat162_rn(
                    fmaxf(acc[mf][nf][2] + bx, 0.f),
                    fmaxf(acc[mf][nf][3] + by, 0.f));
                *(uint32_t*)&hb[(size_t)(rg + 8) * NHID + cg] = *reinterpret_cast<uint32_t*>(&o);
            }
        }
    }
}

// ---------------- GEMM2: h2h = fp16(hb @ W2 + b2) via bf16 mma.sync ----------
#define G2_ASTR 24
#define G2_BSTR 264

__global__ void __launch_bounds__(128)
gemm2_bf16_kernel(const __nv_bfloat16* __restrict__ hb,
                  const __nv_bfloat16* __restrict__ w2t,
                  const float* __restrict__ b2, __half* __restrict__ h2h)
{
    __shared__ __nv_bfloat16 As[2][256][G2_ASTR];
    __shared__ __nv_bfloat16 Bs[NCLASS][G2_BSTR];

    const int tid  = threadIdx.x;
    const int warp = tid >> 5;
    const int lane = tid & 31;
    const int grp  = lane >> 2;
    const int tig  = lane & 3;

    const int r0 = blockIdx.x * 256;

    const uint32_t sA = (uint32_t)__cvta_generic_to_shared(&As[0][0][0]);
    const uint32_t ABUF = 256u * G2_ASTR * 2u;

    #pragma unroll
    for (int i = 0; i < 10; i++) {
        int c = tid + i * 128;
        int n = c >> 5;
        int ks = (c & 31) * 8;
        *(uint4*)&Bs[n][ks] = *(const uint4*)&w2t[(size_t)n * NHID + ks];
    }

    float acc[4][5][4];
    #pragma unroll
    for (int i = 0; i < 4; i++)
        #pragma unroll
        for (int j = 0; j < 5; j++)
            #pragma unroll
            for (int r = 0; r < 4; r++) acc[i][j][r] = 0.f;

    const int NT = NHID / 16;   // 16
    auto load_tile = [&](int kt, int b) {
        const uint32_t ab = sA + (uint32_t)b * ABUF;
        #pragma unroll
        for (int i = 0; i < 4; i++) {
            int c = tid + i * 128;
            int row = c >> 1;
            int seg = (c & 1) * 8;
            int gr = min(r0 + row, N_NODES - 1);
            cp_async16(ab + (uint32_t)((row * G2_ASTR + seg) * 2),
                       hb + (size_t)gr * NHID + kt * 16 + seg);
        }
    };

    load_tile(0, 0);
    cp_commit();
    __syncthreads();

    for (int kt = 0; kt < NT; kt++) {
        if (kt + 1 < NT) load_tile(kt + 1, (kt + 1) & 1);
        cp_commit();
        cp_wait1();
        __syncthreads();

        const int buf = kt & 1;
        uint32_t a[4][4], b[5][2];
        #pragma unroll
        for (int mf = 0; mf < 4; mf++) {
            const int r = warp * 64 + mf * 16 + grp;
            a[mf][0] = *(const uint32_t*)&As[buf][r    ][tig * 2    ];
            a[mf][1] = *(const uint32_t*)&As[buf][r + 8][tig * 2    ];
            a[mf][2] = *(const uint32_t*)&As[buf][r    ][tig * 2 + 8];
            a[mf][3] = *(const uint32_t*)&As[buf][r + 8][tig * 2 + 8];
        }
        #pragma unroll
        for (int nf = 0; nf < 5; nf++) {
            const int cn = nf * 8 + grp;
            b[nf][0] = *(const uint32_t*)&Bs[cn][kt * 16 + tig * 2    ];
            b[nf][1] = *(const uint32_t*)&Bs[cn][kt * 16 + tig * 2 + 8];
        }
        #pragma unroll
        for (int mf = 0; mf < 4; mf++)
            #pragma unroll
            for (int nf = 0; nf < 5; nf++) {
                asm volatile(
                    "mma.sync.aligned.m16n8k16.row.col.f32.bf16.bf16.f32 "
                    "{%0,%1,%2,%3}, {%4,%5,%6,%7}, {%8,%9}, {%0,%1,%2,%3};\n"
                    : "+f"(acc[mf][nf][0]), "+f"(acc[mf][nf][1]),
                      "+f"(acc[mf][nf][2]), "+f"(acc[mf][nf][3])
                    : "r"(a[mf][0]), "r"(a[mf][1]), "r"(a[mf][2]), "r"(a[mf][3]),
                      "r"(b[nf][0]), "r"(b[nf][1]));
            }
        __syncthreads();
    }

    #pragma unroll
    for (int nf = 0; nf < 5; nf++) {
        const int col = nf * 8 + 2 * tig;
        const float bx = b2[col], by = b2[col + 1];
        #pragma unroll
        for (int mf = 0; mf < 4; mf++) {
            const int rg = r0 + warp * 64 + mf * 16 + grp;
            if (rg < N_NODES) {
                __half2 o = __floats2half2_rn(acc[mf][nf][0] + bx,
                                              acc[mf][nf][1] + by);
                *(uint32_t*)&h2h[(size_t)rg * NCLASS + col] = *reinterpret_cast<uint32_t*>(&o);
            }
            if (rg + 8 < N_NODES) {
                __half2 o = __floats2half2_rn(acc[mf][nf][2] + bx,
                                              acc[mf][nf][3] + by);
                *(uint32_t*)&h2h[(size_t)(rg + 8) * NCLASS + col] = *reinterpret_cast<uint32_t*>(&o);
            }
        }
    }
}

// ================= CSR build (by dst), full-chip 3-phase scan ================
__global__ void __launch_bounds__(256)
zero_deg_kernel(int* __restrict__ deg)
{
    int i = blockIdx.x * 256 + threadIdx.x;
    if (i < N_NODES) deg[i] = 0;
}

__global__ void __launch_bounds__(256)
hist_kernel(const int* __restrict__ edst, int* __restrict__ deg)
{
    int e = blockIdx.x * 256 + threadIdx.x;
    if (e < NEDGE) atomicAdd(&deg[edst[e]], 1);
}

__global__ void __launch_bounds__(256)
partial_kernel(const int* __restrict__ deg, int* __restrict__ bpart)
{
    __shared__ int red[256];
    const int tid = threadIdx.x;
    const int i = blockIdx.x * 256 + tid;
    red[tid] = (i < N_NODES) ? deg[i] : 0;
    __syncthreads();
    #pragma unroll
    for (int off = 128; off > 0; off >>= 1) {
        if (tid < off) red[tid] += red[tid + off];
        __syncthreads();
    }
    if (tid == 0) bpart[blockIdx.x] = red[0];
}

__global__ void __launch_bounds__(512)
scanpart_kernel(const int* __restrict__ bpart, int* __restrict__ boff)
{
    __shared__ int s[512];
    const int tid = threadIdx.x;
    int v = (tid < NBLK) ? bpart[tid] : 0;
    s[tid] = v;
    __syncthreads();
    for (int off = 1; off < 512; off <<= 1) {
        int t = (tid >= off) ? s[tid - off] : 0;
        __syncthreads();
        s[tid] += t;
        __syncthreads();
    }
    if (tid < NBLK) boff[tid] = s[tid] - v;   // exclusive
}

__global__ void __launch_bounds__(256)
rowptr_kernel(const int* __restrict__ deg, const int* __restrict__ boff,
              int* __restrict__ rowptr, int* __restrict__ cursor)
{
    __shared__ int s[256];
    const int tid = threadIdx.x;
    const int i = blockIdx.x * 256 + tid;
    int v = (i < N_NODES) ? deg[i] : 0;
    s[tid] = v;
    __syncthreads();
    for (int off = 1; off < 256; off <<= 1) {
        int t = (tid >= off) ? s[tid - off] : 0;
        __syncthreads();
        s[tid] += t;
        __syncthreads();
    }
    const int base = boff[blockIdx.x];
    if (i < N_NODES) {
        int excl = base + s[tid] - v;
        rowptr[i] = excl;
        cursor[i] = excl;
        if (i == N_NODES - 1) rowptr[N_NODES] = excl + v;
    }
}

__global__ void __launch_bounds__(256)
scatter_kernel(const int* __restrict__ esrc, const int* __restrict__ edst,
               const float* __restrict__ eval_, int* __restrict__ cursor,
               int2* __restrict__ cedge)
{
    int e = blockIdx.x * 256 + threadIdx.x;
    if (e < NEDGE) {
        int d = edst[e];
        int slot = atomicAdd(&cursor[d], 1);
        cedge[slot] = make_int2(esrc[e],
                                __float_as_int((1.0f - ALPHA_F) * eval_[e]));
    }
}

// ======== propagation hop: zout[dst] = alpha*h2h[dst] + sum ev*zin[src] ======
// z iterate fp16 in/out (OUT16=0 -> fp32 for the final hop); fp32 accumulation;
// unroll 8 for MLP=8 (halves dependent L2 trips vs unroll 4).
template<int OUT16>
__global__ void __launch_bounds__(256)
prop_kernel(const int* __restrict__ rowptr, const int2* __restrict__ cedge,
            const __half* __restrict__ h2h,
            const __half* __restrict__ zin, void* __restrict__ zout_)
{
    int idx = blockIdx.x * 256 + threadIdx.x;
    if (idx >= N_NODES * 10) return;
    int dst = idx / 10;
    int g = idx - dst * 10;
    const int col = g * 4;

    int e  = rowptr[dst];
    int e1 = rowptr[dst + 1];

    auto loadz = [&](int src) -> float4 {
        const __half* z = zin + (size_t)src * NCLASS + col;
        uint2 r = __ldg((const uint2*)z);
        __half2 p0 = *reinterpret_cast<__half2*>(&r.x);
        __half2 p1 = *reinterpret_cast<__half2*>(&r.y);
        float2 f0 = __half22float2(p0);
        float2 f1 = __half22float2(p1);
        return make_float4(f0.x, f0.y, f1.x, f1.y);
    };

    // teleport term from fp16 h2
    float4 acc0, acc1;
    {
        uint2 r = __ldg((const uint2*)(h2h + (size_t)dst * NCLASS + col));
        __half2 p0 = *reinterpret_cast<__half2*>(&r.x);
        __half2 p1 = *reinterpret_cast<__half2*>(&r.y);
        float2 f0 = __half22float2(p0);
        float2 f1 = __half22float2(p1);
        acc0 = make_float4(ALPHA_F * f0.x, ALPHA_F * f0.y,
                           ALPHA_F * f1.x, ALPHA_F * f1.y);
        acc1 = make_float4(0.f, 0.f, 0.f, 0.f);
    }

    for (; e + 8 <= e1; e += 8) {
        int2 d0 = cedge[e    ], d1 = cedge[e + 1], d2 = cedge[e + 2], d3 = cedge[e + 3];
        int2 d4 = cedge[e + 4], d5 = cedge[e + 5], d6 = cedge[e + 6], d7 = cedge[e + 7];
        float4 z0 = loadz(d0.x), z1 = loadz(d1.x), z2 = loadz(d2.x), z3 = loadz(d3.x);
        float4 z4 = loadz(d4.x), z5 = loadz(d5.x), z6 = loadz(d6.x), z7 = loadz(d7.x);
        float v0 = __int_as_float(d0.y), v1 = __int_as_float(d1.y);
        float v2 = __int_as_float(d2.y), v3 = __int_as_float(d3.y);
        float v4 = __int_as_float(d4.y), v5 = __int_as_float(d5.y);
        float v6 = __int_as_float(d6.y), v7 = __int_as_float(d7.y);
        acc0.x = fmaf(v0, z0.x, acc0.x); acc0.y = fmaf(v0, z0.y, acc0.y);
        acc0.z = fmaf(v0, z0.z, acc0.z); acc0.w = fmaf(v0, z0.w, acc0.w);
        acc1.x = fmaf(v1, z1.x, acc1.x); acc1.y = fmaf(v1, z1.y, acc1.y);
        acc1.z = fmaf(v1, z1.z, acc1.z); acc1.w = fmaf(v1, z1.w, acc1.w);
        acc0.x = fmaf(v2, z2.x, acc0.x); acc0.y = fmaf(v2, z2.y, acc0.y);
        acc0.z = fmaf(v2, z2.z, acc0.z); acc0.w = fmaf(v2, z2.w, acc0.w);
        acc1.x = fmaf(v3, z3.x, acc1.x); acc1.y = fmaf(v3, z3.y, acc1.y);
        acc1.z = fmaf(v3, z3.z, acc1.z); acc1.w = fmaf(v3, z3.w, acc1.w);
        acc0.x = fmaf(v4, z4.x, acc0.x); acc0.y = fmaf(v4, z4.y, acc0.y);
        acc0.z = fmaf(v4, z4.z, acc0.z); acc0.w = fmaf(v4, z4.w, acc0.w);
        acc1.x = fmaf(v5, z5.x, acc1.x); acc1.y = fmaf(v5, z5.y, acc1.y);
        acc1.z = fmaf(v5, z5.z, acc1.z); acc1.w = fmaf(v5, z5.w, acc1.w);
        acc0.x = fmaf(v6, z6.x, acc0.x); acc0.y = fmaf(v6, z6.y, acc0.y);
        acc0.z = fmaf(v6, z6.z, acc0.z); acc0.w = fmaf(v6, z6.w, acc0.w);
        acc1.x = fmaf(v7, z7.x, acc1.x); acc1.y = fmaf(v7, z7.y, acc1.y);
        acc1.z = fmaf(v7, z7.z, acc1.z); acc1.w = fmaf(v7, z7.w, acc1.w);
    }
    for (; e + 2 <= e1; e += 2) {
        int2 d0 = cedge[e], d1 = cedge[e + 1];
        float4 z0 = loadz(d0.x), z1 = loadz(d1.x);
        float v0 = __int_as_float(d0.y), v1 = __int_as_float(d1.y);
        acc0.x = fmaf(v0, z0.x, acc0.x); acc0.y = fmaf(v0, z0.y, acc0.y);
        acc0.z = fmaf(v0, z0.z, acc0.z); acc0.w = fmaf(v0, z0.w, acc0.w);
        acc1.x = fmaf(v1, z1.x, acc1.x); acc1.y = fmaf(v1, z1.y, acc1.y);
        acc1.z = fmaf(v1, z1.z, acc1.z); acc1.w = fmaf(v1, z1.w, acc1.w);
    }
    if (e < e1) {
        int2 d0 = cedge[e];
        float4 z0 = loadz(d0.x);
        float v0 = __int_as_float(d0.y);
        acc0.x = fmaf(v0, z0.x, acc0.x); acc0.y = fmaf(v0, z0.y, acc0.y);
        acc0.z = fmaf(v0, z0.z, acc0.z); acc0.w = fmaf(v0, z0.w, acc0.w);
    }
    acc0.x += acc1.x; acc0.y += acc1.y; acc0.z += acc1.z; acc0.w += acc1.w;

    if (OUT16) {
        __half2 p0 = __floats2half2_rn(acc0.x, acc0.y);
        __half2 p1 = __floats2half2_rn(acc0.z, acc0.w);
        uint2 o;
        o.x = *reinterpret_cast<uint32_t*>(&p0);
        o.y = *reinterpret_cast<uint32_t*>(&p1);
        *(uint2*)((__half*)zout_ + (size_t)dst * NCLASS + col) = o;
    } else {
        *(float4*)((float*)zout_ + (size_t)dst * NCLASS + col) = acc0;
    }
}

// ---------------- log_softmax per row ----------------
__global__ void __launch_bounds__(256)
softmax_kernel(const float* __restrict__ z, float* __restrict__ out)
{
    int row = blockIdx.x * 8 + (threadIdx.x >> 5);
    int lane = threadIdx.x & 31;
    if (row >= N_NODES) return;
    const float* zr = z + (size_t)row * NCLASS;
    float v0 = zr[lane];
    bool has2 = (lane + 32) < NCLASS;
    float v1 = has2 ? zr[lane + 32] : -3.402823466e38f;
    float m = fmaxf(v0, v1);
    #pragma unroll
    for (int o = 16; o > 0; o >>= 1) m = fmaxf(m, __shfl_xor_sync(0xffffffffu, m, o));
    float s = __expf(v0 - m) + (has2 ? __expf(v1 - m) : 0.f);
    #pragma unroll
    for (int o = 16; o > 0; o >>= 1) s += __shfl_xor_sync(0xffffffffu, s, o);
    float lse = m + __logf(s);
    float* orow = out + (size_t)row * NCLASS;
    orow[lane] = v0 - lse;
    if (has2) orow[lane + 32] = v1 - lse;
}

// ---------------- launch ----------------
extern "C" void kernel_launch(void* const* d_in, const int* in_sizes, int n_in,
                              void* d_out, int out_size)
{
    const float* x     = (const float*)d_in[0];
    const int*   esrc  = (const int*)  d_in[1];
    const int*   edst  = (const int*)  d_in[2];
    const float* eval_ = (const float*)d_in[3];
    const float* W1    = (const float*)d_in[4];
    const float* b1    = (const float*)d_in[5];
    const float* W2    = (const float*)d_in[6];
    const float* b2    = (const float*)d_in[7];
    float* out = (float*)d_out;

    __half *h2h, *zha, *zhb;
    __nv_bfloat16 *hb, *xb, *w1b, *w2t;
    int *deg, *rowptr, *cursor, *bpart, *boff;
    int2 *cedge;
    cudaGetSymbolAddress((void**)&hb,     g_hb);
    cudaGetSymbolAddress((void**)&h2h,    g_h2h);
    cudaGetSymbolAddress((void**)&zha,    g_zha);
    cudaGetSymbolAddress((void**)&zhb,    g_zhb);
    cudaGetSymbolAddress((void**)&xb,     g_xb);
    cudaGetSymbolAddress((void**)&w1b,    g_w1b);
    cudaGetSymbolAddress((void**)&w2t,    g_w2t);
    cudaGetSymbolAddress((void**)&deg,    g_deg);
    cudaGetSymbolAddress((void**)&rowptr, g_rowptr);
    cudaGetSymbolAddress((void**)&cursor, g_cursor);
    cudaGetSymbolAddress((void**)&bpart,  g_bpart);
    cudaGetSymbolAddress((void**)&boff,   g_boff);
    cudaGetSymbolAddress((void**)&cedge,  g_cedge);

    // bf16 conversions
    conv_x_kernel<<<(N_NODES * NFEAT / 8 + 255) / 256, 256>>>(x, xb);
    conv_w1_kernel<<<(NHID * NFEAT + 255) / 256, 256>>>(W1, w1b);
    conv_w2_kernel<<<(NCLASS * NHID + 255) / 256, 256>>>(W2, w2t);

    // GEMM1 (bf16 mma.sync + ldmatrix) -> hb (bf16)
    dim3 g1((N_NODES + 127) / 128, NHID / 128);   // (782, 2)
    gemm1_bf16_kernel<<<g1, 256>>>(xb, w1b, b1, hb);

    // GEMM2 (bf16 mma.sync) -> h2h (fp16)
    gemm2_bf16_kernel<<<(N_NODES + 255) / 256, 128>>>(hb, w2t, b2, h2h);

    // CSR build (full-chip scan)
    zero_deg_kernel<<<NBLK, 256>>>(deg);
    hist_kernel<<<(NEDGE + 255) / 256, 256>>>(edst, deg);
    partial_kernel<<<NBLK, 256>>>(deg, bpart);
    scanpart_kernel<<<1, 512>>>(bpart, boff);
    rowptr_kernel<<<NBLK, 256>>>(deg, boff, rowptr, cursor);
    scatter_kernel<<<(NEDGE + 255) / 256, 256>>>(esrc, edst, eval_, cursor, cedge);

    const int prop_blocks = (N_NODES * 10 + 255) / 256;

    // hop 0: zin = h2h (fp16) -> zha
    prop_kernel<1><<<prop_blocks, 256>>>(rowptr, cedge, h2h, h2h, zha);
    // hops 1..8: fp16 ping-pong
    const __half* zi = zha;
    __half* zo = zhb;
    for (int i = 1; i < KHOPS - 1; i++) {
        prop_kernel<1><<<prop_blocks, 256>>>(rowptr, cedge, h2h, zi, zo);
        const __half* t = zo; zo = (__half*)zi; zi = t;
    }
    // hop 9: fp16 -> fp32 out
    prop_kernel<0><<<prop_blocks, 256>>>(rowptr, cedge, h2h, zi, out);

    softmax_kernel<<<(N_NODES + 7) / 8, 256>>>(out, out);
}

// round 16
// speedup vs baseline: 2.6818x; 1.0147x over previous
#include <cuda_runtime.h>
#include <cuda_bf16.h>
#include <cuda_fp16.h>
#include <cstdint>
#include <math.h>

#define N_NODES 100000
#define NFEAT   512
#define NHID    256
#define NCLASS  40
#define NEDGE   1600000
#define KHOPS   10
#define ALPHA_F 0.1f
#define NBLK    391   // ceil(100000/256)

// ---------------- scratch (device globals; no allocs allowed) ----------------
__device__ float          g_h2f[(size_t)N_NODES * NCLASS]; // 16 MB (fp32 h2 accum)
__device__ __half         g_h2h[(size_t)N_NODES * NCLASS]; // 8 MB (fp16 h2)
__device__ __half         g_zha[(size_t)N_NODES * NCLASS]; // 8 MB (fp16 z ping)
__device__ __half         g_zhb[(size_t)N_NODES * NCLASS]; // 8 MB (fp16 z pong)
__device__ __nv_bfloat16  g_xb [(size_t)N_NODES * NFEAT];  // 102.4 MB (bf16 x)
__device__ __nv_bfloat16  g_w1b[(size_t)NHID * NFEAT];     // 256 KB (W1^T bf16 [N][K])
__device__ __nv_bfloat16  g_w2t[(size_t)NCLASS * NHID];    // 20 KB (W2^T bf16 [N][K])
__device__ int   g_deg[N_NODES];
__device__ int   g_rowptr[N_NODES + 1];
__device__ int   g_cursor[N_NODES];
__device__ int   g_bpart[512];
__device__ int   g_boff[512];
__device__ int2  g_cedge[NEDGE];                           // 12.8 MB {src, val bits}

// ---------------- PTX helpers ----------------
__device__ __forceinline__ void cp_async16(uint32_t saddr, const void* gaddr) {
    asm volatile("cp.async.cg.shared.global [%0], [%1], 16;\n" :: "r"(saddr), "l"(gaddr));
}
__device__ __forceinline__ void cp_commit() {
    asm volatile("cp.async.commit_group;\n" ::: "memory");
}
__device__ __forceinline__ void cp_wait1() {
    asm volatile("cp.async.wait_group 1;\n" ::: "memory");
}
__device__ __forceinline__ void ldsm_x4(uint32_t& r0, uint32_t& r1, uint32_t& r2,
                                        uint32_t& r3, uint32_t addr) {
    asm volatile("ldmatrix.sync.aligned.m8n8.x4.shared.b16 {%0,%1,%2,%3}, [%4];"
                 : "=r"(r0), "=r"(r1), "=r"(r2), "=r"(r3) : "r"(addr));
}
__device__ __forceinline__ void red_v2(float* p, float a, float b) {
    asm volatile("red.global.add.v2.f32 [%0], {%1, %2};"
                 :: "l"(p), "f"(a), "f"(b) : "memory");
}

// ---------------- bf16 conversions + h2 init ----------------
__global__ void __launch_bounds__(256)
conv_x_kernel(const float* __restrict__ x, __nv_bfloat16* __restrict__ xb)
{
    int i = blockIdx.x * 256 + threadIdx.x;         // per 8 floats
    const int n8 = N_NODES * NFEAT / 8;
    if (i < n8) {
        float4 a = ((const float4*)x)[2 * i];
        float4 b = ((const float4*)x)[2 * i + 1];
        __nv_bfloat162 p0 = __floats2bfloat162_rn(a.x, a.y);
        __nv_bfloat162 p1 = __floats2bfloat162_rn(a.z, a.w);
        __nv_bfloat162 p2 = __floats2bfloat162_rn(b.x, b.y);
        __nv_bfloat162 p3 = __floats2bfloat162_rn(b.z, b.w);
        uint4 o;
        o.x = *reinterpret_cast<unsigned*>(&p0);
        o.y = *reinterpret_cast<unsigned*>(&p1);
        o.z = *reinterpret_cast<unsigned*>(&p2);
        o.w = *reinterpret_cast<unsigned*>(&p3);
        ((uint4*)xb)[i] = o;
    }
}

__global__ void __launch_bounds__(256)
conv_w1_kernel(const float* __restrict__ W1, __nv_bfloat16* __restrict__ w1b)
{
    int id = blockIdx.x * 256 + threadIdx.x;        // (n,k), k fast
    if (id < NHID * NFEAT) {
        int n = id >> 9;
        int k = id & 511;
        w1b[id] = __float2bfloat16(W1[(size_t)k * NHID + n]);
    }
}

__global__ void __launch_bounds__(256)
conv_w2_kernel(const float* __restrict__ W2, __nv_bfloat16* __restrict__ w2t)
{
    int id = blockIdx.x * 256 + threadIdx.x;        // (n,k), k fast
    if (id < NCLASS * NHID) {
        int n = id >> 8;
        int k = id & 255;
        w2t[id] = __float2bfloat16(W2[(size_t)k * NCLASS + n]);
    }
}

__global__ void __launch_bounds__(256)
zero_h2_kernel(float* __restrict__ h2f)
{
    int i = blockIdx.x * 256 + threadIdx.x;
    const int n4 = N_NODES * NCLASS / 4;
    if (i < n4) ((float4*)h2f)[i] = make_float4(0.f, 0.f, 0.f, 0.f);
}

// h2h = fp16(h2f + b2)
__global__ void __launch_bounds__(256)
conv_h2_kernel(const float* __restrict__ h2f, const float* __restrict__ b2,
               __half* __restrict__ h2h)
{
    int i = blockIdx.x * 256 + threadIdx.x;
    const int n2 = N_NODES * NCLASS / 2;
    if (i < n2) {
        int base = i * 2;
        int col = base % NCLASS;
        float2 v = *(const float2*)&h2f[base];
        __half2 o = __floats2half2_rn(v.x + b2[col], v.y + b2[col + 1]);
        *(uint32_t*)&h2h[base] = *reinterpret_cast<uint32_t*>(&o);
    }
}

// ====== fused GEMM1+GEMM2: per-CTA h-tile (128x128) -> partial h2 via REDG ===
// Mainloop identical to R14 gemm1 (bf16 mma + ldmatrix, double-buffer cp.async).
// Epilogue: stage relu(h)+b1 tile to smem (bf16), load W2^T k-chunk, 8 warps
// run the gemm2 partial (K=128) and red.global.add into fp32 h2f.
#define G1_BK  32
#define G1_STR 40
// smem union region:
//   phase A: As[2][128][40] @0 (20480 B), Bs[2][128][40] @20480 (20480 B)
//   phase B: Hs[128][136]  @0 (34816 B), W2s[40][136] @34816 (10880 B)
#define SM_BS_OFF   20480
#define SM_BUF      10240
#define SM_W2S_OFF  34816
#define SM_TOTAL    45696
#define HS_STR      136

__global__ void __launch_bounds__(256, 2)
gemm_fused_kernel(const __nv_bfloat16* __restrict__ xb,
                  const __nv_bfloat16* __restrict__ w1b,
                  const __nv_bfloat16* __restrict__ w2t,
                  const float* __restrict__ b1, float* __restrict__ h2f)
{
    __shared__ __align__(16) char sm[SM_TOTAL];

    const int tid  = threadIdx.x;
    const int warp = tid >> 5;
    const int lane = tid & 31;
    const int grp  = lane >> 2;
    const int tig  = lane & 3;
    const int warp_m = warp & 1;
    const int warp_n = warp >> 1;

    const int m0 = blockIdx.x * 128;
    const int n0 = blockIdx.y * 128;   // gemm1 N-block == gemm2 K-chunk

    const uint32_t sbase = (uint32_t)__cvta_generic_to_shared(sm);

    const int lm_row = lane & 15;
    const int lm_kof = (lane >> 4) * 8;

    float acc[4][4][4];
    #pragma unroll
    for (int i = 0; i < 4; i++)
        #pragma unroll
        for (int j = 0; j < 4; j++)
            #pragma unroll
            for (int r = 0; r < 4; r++) acc[i][j][r] = 0.f;

    const int c0 = tid, c1 = tid + 256;
    const int ar0 = c0 >> 2, ak0 = (c0 & 3) * 8;
    const int ar1 = c1 >> 2, ak1 = (c1 & 3) * 8;
    const int gr0 = min(m0 + ar0, N_NODES - 1);
    const int gr1 = min(m0 + ar1, N_NODES - 1);

    const int NT = NFEAT / G1_BK;  // 16

    auto load_tile = [&](int kt, int b) {
        const int kb = kt * G1_BK;
        const uint32_t ab = sbase + (uint32_t)b * SM_BUF;
        const uint32_t bb = sbase + SM_BS_OFF + (uint32_t)b * SM_BUF;
        cp_async16(ab + (uint32_t)((ar0 * G1_STR + ak0) * 2),
                   xb + (size_t)gr0 * NFEAT + kb + ak0);
        cp_async16(ab + (uint32_t)((ar1 * G1_STR + ak1) * 2),
                   xb + (size_t)gr1 * NFEAT + kb + ak1);
        cp_async16(bb + (uint32_t)((ar0 * G1_STR + ak0) * 2),
                   w1b + (size_t)(n0 + ar0) * NFEAT + kb + ak0);
        cp_async16(bb + (uint32_t)((ar1 * G1_STR + ak1) * 2),
                   w1b + (size_t)(n0 + ar1) * NFEAT + kb + ak1);
    };

    load_tile(0, 0);
    cp_commit();

    for (int kt = 0; kt < NT; kt++) {
        if (kt + 1 < NT) load_tile(kt + 1, (kt + 1) & 1);
        cp_commit();
        cp_wait1();
        __syncthreads();

        const int buf = kt & 1;
        const uint32_t abuf = sbase + (uint32_t)buf * SM_BUF;
        const uint32_t bbuf = sbase + SM_BS_OFF + (uint32_t)buf * SM_BUF;
        #pragma unroll
        for (int ks = 0; ks < 2; ks++) {
            const int kb = ks * 16 + lm_kof;
            uint32_t a[4][4], b[4][2];
            #pragma unroll
            for (int mf = 0; mf < 4; mf++) {
                const int r = warp_m * 64 + mf * 16 + lm_row;
                ldsm_x4(a[mf][0], a[mf][1], a[mf][2], a[mf][3],
                        abuf + (uint32_t)((r * G1_STR + kb) * 2));
            }
            #pragma unroll
            for (int np = 0; np < 2; np++) {
                const int cn = warp_n * 32 + np * 16 + lm_row;
                ldsm_x4(b[2*np][0], b[2*np + 1][0], b[2*np][1], b[2*np + 1][1],
                        bbuf + (uint32_t)((cn * G1_STR + kb) * 2));
            }
            #pragma unroll
            for (int mf = 0; mf < 4; mf++)
                #pragma unroll
                for (int nf = 0; nf < 4; nf++) {
                    asm volatile(
                        "mma.sync.aligned.m16n8k16.row.col.f32.bf16.bf16.f32 "
                        "{%0,%1,%2,%3}, {%4,%5,%6,%7}, {%8,%9}, {%0,%1,%2,%3};\n"
                        : "+f"(acc[mf][nf][0]), "+f"(acc[mf][nf][1]),
                          "+f"(acc[mf][nf][2]), "+f"(acc[mf][nf][3])
                        : "r"(a[mf][0]), "r"(a[mf][1]), "r"(a[mf][2]), "r"(a[mf][3]),
                          "r"(b[nf][0]), "r"(b[nf][1]));
                }
        }
        __syncthreads();
    }

    // ---- phase B: stage relu(h)+b1 tile to Hs (bf16) + load W2^T chunk ------
    __nv_bfloat16* Hs  = (__nv_bfloat16*)sm;                    // [128][136]
    __nv_bfloat16* W2s = (__nv_bfloat16*)(sm + SM_W2S_OFF);     // [40][136]

    #pragma unroll
    for (int nf = 0; nf < 4; nf++) {
        const int cl = warp_n * 32 + nf * 8 + 2 * tig;          // local col
        const float bx = b1[n0 + cl], by = b1[n0 + cl + 1];
        #pragma unroll
        for (int mf = 0; mf < 4; mf++) {
            const int rl = warp_m * 64 + mf * 16 + grp;          // local row
            __nv_bfloat162 o0 = __floats2bfloat162_rn(
                fmaxf(acc[mf][nf][0] + bx, 0.f),
                fmaxf(acc[mf][nf][1] + by, 0.f));
            *(uint32_t*)&Hs[rl * HS_STR + cl] = *reinterpret_cast<uint32_t*>(&o0);
            __nv_bfloat162 o1 = __floats2bfloat162_rn(
                fmaxf(acc[mf][nf][2] + bx, 0.f),
                fmaxf(acc[mf][nf][3] + by, 0.f));
            *(uint32_t*)&Hs[(rl + 8) * HS_STR + cl] = *reinterpret_cast<uint32_t*>(&o1);
        }
    }
    // W2s[c][kl] = w2t[c][n0 + kl]; 40*128 bf16 = 640 x 8-elem chunks
    for (int t = tid; t < 640; t += 256) {
        int c  = t >> 4;
        int kl = (t & 15) * 8;
        *(uint4*)&W2s[c * HS_STR + kl] =
            *(const uint4*)&w2t[(size_t)c * NHID + n0 + kl];
    }
    __syncthreads();

    // ---- gemm2 partial: warp w -> rows m0 + w*16 + {grp, grp+8} -------------
    {
        float a2[5][4];
        #pragma unroll
        for (int j = 0; j < 5; j++)
            #pragma unroll
            for (int r = 0; r < 4; r++) a2[j][r] = 0.f;

        #pragma unroll
        for (int kt2 = 0; kt2 < 8; kt2++) {
            const int kb = kt2 * 16;
            uint32_t a[4], b[5][2];
            const int r = warp * 16 + grp;
            a[0] = *(const uint32_t*)&Hs[ r      * HS_STR + kb + tig * 2    ];
            a[1] = *(const uint32_t*)&Hs[(r + 8) * HS_STR + kb + tig * 2    ];
            a[2] = *(const uint32_t*)&Hs[ r      * HS_STR + kb + tig * 2 + 8];
            a[3] = *(const uint32_t*)&Hs[(r + 8) * HS_STR + kb + tig * 2 + 8];
            #pragma unroll
            for (int nf = 0; nf < 5; nf++) {
                const int cn = nf * 8 + grp;
                b[nf][0] = *(const uint32_t*)&W2s[cn * HS_STR + kb + tig * 2    ];
                b[nf][1] = *(const uint32_t*)&W2s[cn * HS_STR + kb + tig * 2 + 8];
            }
            #pragma unroll
            for (int nf = 0; nf < 5; nf++) {
                asm volatile(
                    "mma.sync.aligned.m16n8k16.row.col.f32.bf16.bf16.f32 "
                    "{%0,%1,%2,%3}, {%4,%5,%6,%7}, {%8,%9}, {%0,%1,%2,%3};\n"
                    : "+f"(a2[nf][0]), "+f"(a2[nf][1]),
                      "+f"(a2[nf][2]), "+f"(a2[nf][3])
                    : "r"(a[0]), "r"(a[1]), "r"(a[2]), "r"(a[3]),
                      "r"(b[nf][0]), "r"(b[nf][1]));
            }
        }

        const int rg = m0 + warp * 16 + grp;
        #pragma unroll
        for (int nf = 0; nf < 5; nf++) {
            const int col = nf * 8 + 2 * tig;
            if (rg < N_NODES)
                red_v2(&h2f[(size_t)rg * NCLASS + col], a2[nf][0], a2[nf][1]);
            if (rg + 8 < N_NODES)
                red_v2(&h2f[(size_t)(rg + 8) * NCLASS + col], a2[nf][2], a2[nf][3]);
        }
    }
}

// ================= CSR build (by dst), full-chip 3-phase scan ================
__global__ void __launch_bounds__(256)
zero_deg_kernel(int* __restrict__ deg)
{
    int i = blockIdx.x * 256 + threadIdx.x;
    if (i < N_NODES) deg[i] = 0;
}

__global__ void __launch_bounds__(256)
hist_kernel(const int* __restrict__ edst, int* __restrict__ deg)
{
    int e = blockIdx.x * 256 + threadIdx.x;
    if (e < NEDGE) atomicAdd(&deg[edst[e]], 1);
}

__global__ void __launch_bounds__(256)
partial_kernel(const int* __restrict__ deg, int* __restrict__ bpart)
{
    __shared__ int red[256];
    const int tid = threadIdx.x;
    const int i = blockIdx.x * 256 + tid;
    red[tid] = (i < N_NODES) ? deg[i] : 0;
    __syncthreads();
    #pragma unroll
    for (int off = 128; off > 0; off >>= 1) {
        if (tid < off) red[tid] += red[tid + off];
        __syncthreads();
    }
    if (tid == 0) bpart[blockIdx.x] = red[0];
}

__global__ void __launch_bounds__(512)
scanpart_kernel(const int* __restrict__ bpart, int* __restrict__ boff)
{
    __shared__ int s[512];
    const int tid = threadIdx.x;
    int v = (tid < NBLK) ? bpart[tid] : 0;
    s[tid] = v;
    __syncthreads();
    for (int off = 1; off < 512; off <<= 1) {
        int t = (tid >= off) ? s[tid - off] : 0;
        __syncthreads();
        s[tid] += t;
        __syncthreads();
    }
    if (tid < NBLK) boff[tid] = s[tid] - v;   // exclusive
}

__global__ void __launch_bounds__(256)
rowptr_kernel(const int* __restrict__ deg, const int* __restrict__ boff,
              int* __restrict__ rowptr, int* __restrict__ cursor)
{
    __shared__ int s[256];
    const int tid = threadIdx.x;
    const int i = blockIdx.x * 256 + tid;
    int v = (i < N_NODES) ? deg[i] : 0;
    s[tid] = v;
    __syncthreads();
    for (int off = 1; off < 256; off <<= 1) {
        int t = (tid >= off) ? s[tid - off] : 0;
        __syncthreads();
        s[tid] += t;
        __syncthreads();
    }
    const int base = boff[blockIdx.x];
    if (i < N_NODES) {
        int excl = base + s[tid] - v;
        rowptr[i] = excl;
        cursor[i] = excl;
        if (i == N_NODES - 1) rowptr[N_NODES] = excl + v;
    }
}

__global__ void __launch_bounds__(256)
scatter_kernel(const int* __restrict__ esrc, const int* __restrict__ edst,
               const float* __restrict__ eval_, int* __restrict__ cursor,
               int2* __restrict__ cedge)
{
    int e = blockIdx.x * 256 + threadIdx.x;
    if (e < NEDGE) {
        int d = edst[e];
        int slot = atomicAdd(&cursor[d], 1);
        cedge[slot] = make_int2(esrc[e],
                                __float_as_int((1.0f - ALPHA_F) * eval_[e]));
    }
}

// ======== propagation hop: zout[dst] = alpha*h2h[dst] + sum ev*zin[src] ======
template<int OUT16>
__global__ void __launch_bounds__(256)
prop_kernel(const int* __restrict__ rowptr, const int2* __restrict__ cedge,
            const __half* __restrict__ h2h,
            const __half* __restrict__ zin, void* __restrict__ zout_)
{
    int idx = blockIdx.x * 256 + threadIdx.x;
    if (idx >= N_NODES * 10) return;
    int dst = idx / 10;
    int g = idx - dst * 10;
    const int col = g * 4;

    int e  = rowptr[dst];
    int e1 = rowptr[dst + 1];

    auto loadz = [&](int src) -> float4 {
        const __half* z = zin + (size_t)src * NCLASS + col;
        uint2 r = __ldg((const uint2*)z);
        __half2 p0 = *reinterpret_cast<__half2*>(&r.x);
        __half2 p1 = *reinterpret_cast<__half2*>(&r.y);
        float2 f0 = __half22float2(p0);
        float2 f1 = __half22float2(p1);
        return make_float4(f0.x, f0.y, f1.x, f1.y);
    };

    float4 acc0, acc1;
    {
        uint2 r = __ldg((const uint2*)(h2h + (size_t)dst * NCLASS + col));
        __half2 p0 = *reinterpret_cast<__half2*>(&r.x);
        __half2 p1 = *reinterpret_cast<__half2*>(&r.y);
        float2 f0 = __half22float2(p0);
        float2 f1 = __half22float2(p1);
        acc0 = make_float4(ALPHA_F * f0.x, ALPHA_F * f0.y,
                           ALPHA_F * f1.x, ALPHA_F * f1.y);
        acc1 = make_float4(0.f, 0.f, 0.f, 0.f);
    }

    for (; e + 8 <= e1; e += 8) {
        int2 d0 = cedge[e    ], d1 = cedge[e + 1], d2 = cedge[e + 2], d3 = cedge[e + 3];
        int2 d4 = cedge[e + 4], d5 = cedge[e + 5], d6 = cedge[e + 6], d7 = cedge[e + 7];
        float4 z0 = loadz(d0.x), z1 = loadz(d1.x), z2 = loadz(d2.x), z3 = loadz(d3.x);
        float4 z4 = loadz(d4.x), z5 = loadz(d5.x), z6 = loadz(d6.x), z7 = loadz(d7.x);
        float v0 = __int_as_float(d0.y), v1 = __int_as_float(d1.y);
        float v2 = __int_as_float(d2.y), v3 = __int_as_float(d3.y);
        float v4 = __int_as_float(d4.y), v5 = __int_as_float(d5.y);
        float v6 = __int_as_float(d6.y), v7 = __int_as_float(d7.y);
        acc0.x = fmaf(v0, z0.x, acc0.x); acc0.y = fmaf(v0, z0.y, acc0.y);
        acc0.z = fmaf(v0, z0.z, acc0.z); acc0.w = fmaf(v0, z0.w, acc0.w);
        acc1.x = fmaf(v1, z1.x, acc1.x); acc1.y = fmaf(v1, z1.y, acc1.y);
        acc1.z = fmaf(v1, z1.z, acc1.z); acc1.w = fmaf(v1, z1.w, acc1.w);
        acc0.x = fmaf(v2, z2.x, acc0.x); acc0.y = fmaf(v2, z2.y, acc0.y);
        acc0.z = fmaf(v2, z2.z, acc0.z); acc0.w = fmaf(v2, z2.w, acc0.w);
        acc1.x = fmaf(v3, z3.x, acc1.x); acc1.y = fmaf(v3, z3.y, acc1.y);
        acc1.z = fmaf(v3, z3.z, acc1.z); acc1.w = fmaf(v3, z3.w, acc1.w);
        acc0.x = fmaf(v4, z4.x, acc0.x); acc0.y = fmaf(v4, z4.y, acc0.y);
        acc0.z = fmaf(v4, z4.z, acc0.z); acc0.w = fmaf(v4, z4.w, acc0.w);
        acc1.x = fmaf(v5, z5.x, acc1.x); acc1.y = fmaf(v5, z5.y, acc1.y);
        acc1.z = fmaf(v5, z5.z, acc1.z); acc1.w = fmaf(v5, z5.w, acc1.w);
        acc0.x = fmaf(v6, z6.x, acc0.x); acc0.y = fmaf(v6, z6.y, acc0.y);
        acc0.z = fmaf(v6, z6.z, acc0.z); acc0.w = fmaf(v6, z6.w, acc0.w);
        acc1.x = fmaf(v7, z7.x, acc1.x); acc1.y = fmaf(v7, z7.y, acc1.y);
        acc1.z = fmaf(v7, z7.z, acc1.z); acc1.w = fmaf(v7, z7.w, acc1.w);
    }
    for (; e + 2 <= e1; e += 2) {
        int2 d0 = cedge[e], d1 = cedge[e + 1];
        float4 z0 = loadz(d0.x), z1 = loadz(d1.x);
        float v0 = __int_as_float(d0.y), v1 = __int_as_float(d1.y);
        acc0.x = fmaf(v0, z0.x, acc0.x); acc0.y = fmaf(v0, z0.y, acc0.y);
        acc0.z = fmaf(v0, z0.z, acc0.z); acc0.w = fmaf(v0, z0.w, acc0.w);
        acc1.x = fmaf(v1, z1.x, acc1.x); acc1.y = fmaf(v1, z1.y, acc1.y);
        acc1.z = fmaf(v1, z1.z, acc1.z); acc1.w = fmaf(v1, z1.w, acc1.w);
    }
    if (e < e1) {
        int2 d0 = cedge[e];
        float4 z0 = loadz(d0.x);
        float v0 = __int_as_float(d0.y);
        acc0.x = fmaf(v0, z0.x, acc0.x); acc0.y = fmaf(v0, z0.y, acc0.y);
        acc0.z = fmaf(v0, z0.z, acc0.z); acc0.w = fmaf(v0, z0.w, acc0.w);
    }
    acc0.x += acc1.x; acc0.y += acc1.y; acc0.z += acc1.z; acc0.w += acc1.w;

    if (OUT16) {
        __half2 p0 = __floats2half2_rn(acc0.x, acc0.y);
        __half2 p1 = __floats2half2_rn(acc0.z, acc0.w);
        uint2 o;
        o.x = *reinterpret_cast<uint32_t*>(&p0);
        o.y = *reinterpret_cast<uint32_t*>(&p1);
        *(uint2*)((__half*)zout_ + (size_t)dst * NCLASS + col) = o;
    } else {
        *(float4*)((float*)zout_ + (size_t)dst * NCLASS + col) = acc0;
    }
}

// ---------------- log_softmax per row ----------------
__global__ void __launch_bounds__(256)
softmax_kernel(const float* __restrict__ z, float* __restrict__ out)
{
    int row = blockIdx.x * 8 + (threadIdx.x >> 5);
    int lane = threadIdx.x & 31;
    if (row >= N_NODES) return;
    const float* zr = z + (size_t)row * NCLASS;
    float v0 = zr[lane];
    bool has2 = (lane + 32) < NCLASS;
    float v1 = has2 ? zr[lane + 32] : -3.402823466e38f;
    float m = fmaxf(v0, v1);
    #pragma unroll
    for (int o = 16; o > 0; o >>= 1) m = fmaxf(m, __shfl_xor_sync(0xffffffffu, m, o));
    float s = __expf(v0 - m) + (has2 ? __expf(v1 - m) : 0.f);
    #pragma unroll
    for (int o = 16; o > 0; o >>= 1) s += __shfl_xor_sync(0xffffffffu, s, o);
    float lse = m + __logf(s);
    float* orow = out + (size_t)row * NCLASS;
    orow[lane] = v0 - lse;
    if (has2) orow[lane + 32] = v1 - lse;
}

// ---------------- launch ----------------
extern "C" void kernel_launch(void* const* d_in, const int* in_sizes, int n_in,
                              void* d_out, int out_size)
{
    const float* x     = (const float*)d_in[0];
    const int*   esrc  = (const int*)  d_in[1];
    const int*   edst  = (const int*)  d_in[2];
    const float* eval_ = (const float*)d_in[3];
    const float* W1    = (const float*)d_in[4];
    const float* b1    = (const float*)d_in[5];
    const float* W2    = (const float*)d_in[6];
    const float* b2    = (const float*)d_in[7];
    float* out = (float*)d_out;

    float *h2f;
    __half *h2h, *zha, *zhb;
    __nv_bfloat16 *xb, *w1b, *w2t;
    int *deg, *rowptr, *cursor, *bpart, *boff;
    int2 *cedge;
    cudaGetSymbolAddress((void**)&h2f,    g_h2f);
    cudaGetSymbolAddress((void**)&h2h,    g_h2h);
    cudaGetSymbolAddress((void**)&zha,    g_zha);
    cudaGetSymbolAddress((void**)&zhb,    g_zhb);
    cudaGetSymbolAddress((void**)&xb,     g_xb);
    cudaGetSymbolAddress((void**)&w1b,    g_w1b);
    cudaGetSymbolAddress((void**)&w2t,    g_w2t);
    cudaGetSymbolAddress((void**)&deg,    g_deg);
    cudaGetSymbolAddress((void**)&rowptr, g_rowptr);
    cudaGetSymbolAddress((void**)&cursor, g_cursor);
    cudaGetSymbolAddress((void**)&bpart,  g_bpart);
    cudaGetSymbolAddress((void**)&boff,   g_boff);
    cudaGetSymbolAddress((void**)&cedge,  g_cedge);

    // conversions + h2 accumulator init
    conv_x_kernel<<<(N_NODES * NFEAT / 8 + 255) / 256, 256>>>(x, xb);
    conv_w1_kernel<<<(NHID * NFEAT + 255) / 256, 256>>>(W1, w1b);
    conv_w2_kernel<<<(NCLASS * NHID + 255) / 256, 256>>>(W2, w2t);
    zero_h2_kernel<<<(N_NODES * NCLASS / 4 + 255) / 256, 256>>>(h2f);

    // fused GEMM1+GEMM2 -> h2f (fp32, REDG-accumulated)
    dim3 g1((N_NODES + 127) / 128, NHID / 128);   // (782, 2)
    gemm_fused_kernel<<<g1, 256>>>(xb, w1b, w2t, b1, h2f);

    // h2h = fp16(h2f + b2)
    conv_h2_kernel<<<(N_NODES * NCLASS / 2 + 255) / 256, 256>>>(h2f, b2, h2h);

    // CSR build (full-chip scan)
    zero_deg_kernel<<<NBLK, 256>>>(deg);
    hist_kernel<<<(NEDGE + 255) / 256, 256>>>(edst, deg);
    partial_kernel<<<NBLK, 256>>>(deg, bpart);
    scanpart_kernel<<<1, 512>>>(bpart, boff);
    rowptr_kernel<<<NBLK, 256>>>(deg, boff, rowptr, cursor);
    scatter_kernel<<<(NEDGE + 255) / 256, 256>>>(esrc, edst, eval_, cursor, cedge);

    const int prop_blocks = (N_NODES * 10 + 255) / 256;

    // hop 0: zin = h2h (fp16) -> zha
    prop_kernel<1><<<prop_blocks, 256>>>(rowptr, cedge, h2h, h2h, zha);
    // hops 1..8: fp16 ping-pong
    const __half* zi = zha;
    __half* zo = zhb;
    for (int i = 1; i < KHOPS - 1; i++) {
        prop_kernel<1><<<prop_blocks, 256>>>(rowptr, cedge, h2h, zi, zo);
        const __half* t = zo; zo = (__half*)zi; zi = t;
    }
    // hop 9: fp16 -> fp32 out
    prop_kernel<0><<<prop_blocks, 256>>>(rowptr, cedge, h2h, zi, out);

    softmax_kernel<<<(N_NODES + 7) / 8, 256>>>(out, out);
}